// round 1
// baseline (speedup 1.0000x reference)
#include <cuda_runtime.h>
#include <cstdint>

// Problem constants
#define BB   2048      // batch
#define KHIST 200      // history length
#define DD   512       // latent dim
#define HHID 1024      // 2*D
#define CBK  2048      // codebook size
#define BD   (BB*DD)   // 1048576

// ---------------- scratch (device globals; no allocation allowed) ----------
__device__ float g_mean[BB * DD];      // 4 MB
__device__ float g_hidden[BB * HHID];  // 8 MB
__device__ float g_u[BB * DD];         // 4 MB
__device__ float g_scores[BB * CBK];   // 16 MB
__device__ float g_cnorm[CBK];
__device__ int   g_argmin[BB];
__device__ float g_bsum[BB];           // per-block diff partials (deterministic reduce)

// ---------------------------------------------------------------------------
// Kernel 1: masked gather + mean over history.  One block per batch row,
// 128 threads, each thread owns one float4 column of D=512.
// ---------------------------------------------------------------------------
__global__ void __launch_bounds__(128) gather_mean_kernel(
    const int* __restrict__ items, const float* __restrict__ item_embed)
{
    int b = blockIdx.x;
    int t = threadIdx.x;
    __shared__ int sidx[KHIST];
    for (int i = t; i < KHIST; i += 128) sidx[i] = items[b * KHIST + i];
    __syncthreads();

    const float4* E4 = (const float4*)item_embed;
    float4 acc = make_float4(0.f, 0.f, 0.f, 0.f);
    int cnt = 0;
    #pragma unroll 4
    for (int k = 0; k < KHIST; k++) {
        int idx = sidx[k];
        float m = (idx != 0) ? 1.0f : 0.0f;
        cnt += (idx != 0);
        float4 v = E4[(size_t)idx * 128 + t];
        acc.x += m * v.x; acc.y += m * v.y; acc.z += m * v.z; acc.w += m * v.w;
    }
    float inv = 1.0f / (float)cnt;
    float4 r = make_float4(acc.x * inv, acc.y * inv, acc.z * inv, acc.w * inv);
    ((float4*)g_mean)[b * 128 + t] = r;
}

// ---------------------------------------------------------------------------
// Kernel 2: codebook row squared norms.  One block per code, 128 threads.
// ---------------------------------------------------------------------------
__global__ void __launch_bounds__(128) cnorm_kernel(const float* __restrict__ codebook)
{
    int j = blockIdx.x;
    int t = threadIdx.x;
    float4 v = ((const float4*)codebook)[j * 128 + t];
    float s = v.x * v.x + v.y * v.y + v.z * v.z + v.w * v.w;
    // warp reduce
    #pragma unroll
    for (int o = 16; o > 0; o >>= 1) s += __shfl_down_sync(0xffffffffu, s, o);
    __shared__ float red[4];
    if ((t & 31) == 0) red[t >> 5] = s;
    __syncthreads();
    if (t == 0) g_cnorm[j] = red[0] + red[1] + red[2] + red[3];
}

// ---------------------------------------------------------------------------
// GEMM: 64x64 tile, BK=16, 256 threads, 4x4 register tile per thread.
// WHICH=0: g_hidden = relu(g_mean @ W1 + b1)      [2048 x 1024, K=512]
// WHICH=1: g_u      = g_hidden @ W2 + b2          [2048 x 512,  K=1024]
//          also scalar-stores user_embed into d_out slice (4B-aligned only)
// WHICH=2: g_scores = cnorm[n] - 2 * (g_u @ codebook^T)  [2048 x 2048, K=512]
// ---------------------------------------------------------------------------
template<int WHICH>
__global__ void __launch_bounds__(256) gemm64_kernel(
    const float* __restrict__ Bm,    // W1 / W2 / codebook
    const float* __restrict__ bias,  // b1 / b2 / unused
    float* __restrict__ out2,        // user_embed slice of d_out (WHICH==1)
    int N, int Kd)
{
    constexpr bool TRANSB = (WHICH == 2);
    const float* __restrict__ A =
        (WHICH == 0) ? g_mean : (WHICH == 1) ? g_hidden : g_u;
    float* __restrict__ out =
        (WHICH == 0) ? g_hidden : (WHICH == 1) ? g_u : g_scores;

    __shared__ float As[16][64];
    __shared__ float Bs[16][64];

    int tid = threadIdx.x;
    int tx = tid & 15, ty = tid >> 4;
    int bm = blockIdx.y * 64, bn = blockIdx.x * 64;

    float acc[4][4] = {};

    int arow = tid >> 2;          // 0..63
    int ac4  = (tid & 3) * 4;     // 0,4,8,12

    for (int k0 = 0; k0 < Kd; k0 += 16) {
        // load A tile 64x16 (row-major [M,K])
        float4 av = *(const float4*)&A[(size_t)(bm + arow) * Kd + k0 + ac4];
        As[ac4 + 0][arow] = av.x;
        As[ac4 + 1][arow] = av.y;
        As[ac4 + 2][arow] = av.z;
        As[ac4 + 3][arow] = av.w;

        if (!TRANSB) {
            // B is [K,N] row-major; load 16x64 tile
            int brow = tid >> 4;        // 0..15
            int bc4  = (tid & 15) * 4;  // 0..60
            *(float4*)&Bs[brow][bc4] =
                *(const float4*)&Bm[(size_t)(k0 + brow) * N + bn + bc4];
        } else {
            // B logical [K,N] = codebook[N,K]^T; load float4 along K
            int nrow = tid >> 2;        // 0..63
            int kc4  = (tid & 3) * 4;
            float4 bv = *(const float4*)&Bm[(size_t)(bn + nrow) * Kd + k0 + kc4];
            Bs[kc4 + 0][nrow] = bv.x;
            Bs[kc4 + 1][nrow] = bv.y;
            Bs[kc4 + 2][nrow] = bv.z;
            Bs[kc4 + 3][nrow] = bv.w;
        }
        __syncthreads();

        #pragma unroll
        for (int kk = 0; kk < 16; kk++) {
            float4 a4 = *(const float4*)&As[kk][ty * 4];
            float4 b4 = *(const float4*)&Bs[kk][tx * 4];
            float ar[4] = {a4.x, a4.y, a4.z, a4.w};
            float br[4] = {b4.x, b4.y, b4.z, b4.w};
            #pragma unroll
            for (int i = 0; i < 4; i++)
                #pragma unroll
                for (int j = 0; j < 4; j++)
                    acc[i][j] += ar[i] * br[j];
        }
        __syncthreads();
    }

    #pragma unroll
    for (int i = 0; i < 4; i++) {
        int row = bm + ty * 4 + i;
        #pragma unroll
        for (int j = 0; j < 4; j++) {
            int col = bn + tx * 4 + j;
            float v = acc[i][j];
            if (WHICH == 0) {
                v += bias[col];
                v = v > 0.f ? v : 0.f;
                out[(size_t)row * N + col] = v;
            } else if (WHICH == 1) {
                v += bias[col];
                out[(size_t)row * N + col] = v;
                out2[(size_t)row * N + col] = v;   // user_embed into d_out (scalar)
            } else {
                out[(size_t)row * N + col] = g_cnorm[col] - 2.0f * v;
            }
        }
    }
}

// ---------------------------------------------------------------------------
// Kernel 4: per-row argmin over 2048 scores; first-occurrence tie-break.
// ---------------------------------------------------------------------------
__global__ void __launch_bounds__(256) argmin_kernel()
{
    int b = blockIdx.x;
    int t = threadIdx.x;
    const float* s = &g_scores[(size_t)b * CBK];
    float best = 3.0e38f;
    int   bi   = 0x7fffffff;
    for (int j = t; j < CBK; j += 256) {
        float v = s[j];
        if (v < best) { best = v; bi = j; }   // ascending j per-thread -> first occurrence
    }
    __shared__ float sv[256];
    __shared__ int   si[256];
    sv[t] = best; si[t] = bi;
    __syncthreads();
    for (int o = 128; o > 0; o >>= 1) {
        if (t < o) {
            float v2 = sv[t + o]; int i2 = si[t + o];
            if (v2 < sv[t] || (v2 == sv[t] && i2 < si[t])) { sv[t] = v2; si[t] = i2; }
        }
        __syncthreads();
    }
    if (t == 0) g_argmin[b] = si[0];
}

// ---------------------------------------------------------------------------
// Kernel 5: epilogue. Per batch row: q = codebook[id]; quant = u + (q-u);
// pos/neg item gathers; per-block diff partial sum.
// ---------------------------------------------------------------------------
__global__ void __launch_bounds__(128) epilogue_kernel(
    const float* __restrict__ codebook, const float* __restrict__ item_embed,
    const int* __restrict__ pos, const int* __restrict__ neg,
    float* __restrict__ out_q, float* __restrict__ out_pos,
    float* __restrict__ out_neg)
{
    int b = blockIdx.x;
    int t = threadIdx.x;
    int id = g_argmin[b];

    float4 q = ((const float4*)codebook)[(size_t)id * 128 + t];
    float4 u = ((const float4*)g_u)[(size_t)b * 128 + t];
    float4 d = make_float4(q.x - u.x, q.y - u.y, q.z - u.z, q.w - u.w);
    float4 qu = make_float4(u.x + d.x, u.y + d.y, u.z + d.z, u.w + d.w);
    ((float4*)out_q)[(size_t)b * 128 + t] = qu;

    int p = pos[b], n = neg[b];
    ((float4*)out_pos)[(size_t)b * 128 + t] = ((const float4*)item_embed)[(size_t)p * 128 + t];
    ((float4*)out_neg)[(size_t)b * 128 + t] = ((const float4*)item_embed)[(size_t)n * 128 + t];

    float ds = d.x * d.x + d.y * d.y + d.z * d.z + d.w * d.w;
    #pragma unroll
    for (int o = 16; o > 0; o >>= 1) ds += __shfl_down_sync(0xffffffffu, ds, o);
    __shared__ float red[4];
    if ((t & 31) == 0) red[t >> 5] = ds;
    __syncthreads();
    if (t == 0) g_bsum[b] = red[0] + red[1] + red[2] + red[3];
}

// ---------------------------------------------------------------------------
// Kernel 6: deterministic final reduction of diff = mean((q-u)^2).
// Single block, fixed-shape tree -> bit-stable across graph replays.
// ---------------------------------------------------------------------------
__global__ void __launch_bounds__(256) diff_kernel(float* __restrict__ out_diff)
{
    int t = threadIdx.x;
    float s = 0.f;
    #pragma unroll
    for (int i = 0; i < BB / 256; i++) s += g_bsum[t + i * 256];
    __shared__ float sv[256];
    sv[t] = s;
    __syncthreads();
    for (int o = 128; o > 0; o >>= 1) {
        if (t < o) sv[t] += sv[t + o];
        __syncthreads();
    }
    if (t == 0) *out_diff = sv[0] * (1.0f / (float)BD);
}

// ---------------------------------------------------------------------------
extern "C" void kernel_launch(void* const* d_in, const int* in_sizes, int n_in,
                              void* d_out, int out_size)
{
    // metadata order:
    // 0 user_id(int32,B) 1 interacted_items(int32,B*K) 2 pos(int32,B) 3 neg(int32,B)
    // 4 item_embed(f32,(N+1)*D) 5 W1(f32,D*2D) 6 b1(f32,2D) 7 W2(f32,2D*D) 8 b2(f32,D)
    // 9 codebook(f32,CB*D)
    const int*   items      = (const int*)  d_in[1];
    const int*   pos        = (const int*)  d_in[2];
    const int*   neg        = (const int*)  d_in[3];
    const float* item_embed = (const float*)d_in[4];
    const float* W1         = (const float*)d_in[5];
    const float* b1         = (const float*)d_in[6];
    const float* W2         = (const float*)d_in[7];
    const float* b2         = (const float*)d_in[8];
    const float* codebook   = (const float*)d_in[9];

    float* out      = (float*)d_out;
    float* out_q    = out;                 // quant_user  [B,D]
    float* out_pos  = out + (size_t)BD;    // pos_item    [B,D]
    float* out_neg  = out + (size_t)2 * BD;// neg_item    [B,D]
    float* out_diff = out + (size_t)3 * BD;          // scalar
    float* out_ue   = out + (size_t)3 * BD + 1;      // user_embed [B,D] (4B-aligned only)

    gather_mean_kernel<<<BB, 128>>>(items, item_embed);
    cnorm_kernel<<<CBK, 128>>>(codebook);

    gemm64_kernel<0><<<dim3(HHID / 64, BB / 64), 256>>>(W1, b1, nullptr, HHID, DD);
    gemm64_kernel<1><<<dim3(DD / 64,   BB / 64), 256>>>(W2, b2, out_ue,  DD,  HHID);
    gemm64_kernel<2><<<dim3(CBK / 64,  BB / 64), 256>>>(codebook, nullptr, nullptr, CBK, DD);

    argmin_kernel<<<BB, 256>>>();
    epilogue_kernel<<<BB, 128>>>(codebook, item_embed, pos, neg, out_q, out_pos, out_neg);
    diff_kernel<<<1, 256>>>(out_diff);
}

// round 2
// speedup vs baseline: 1.0647x; 1.0647x over previous
#include <cuda_runtime.h>
#include <cstdint>

// Problem constants
#define BB    2048     // batch
#define KHIST 200      // history length
#define DD    512      // latent dim
#define HHID  1024     // 2*D
#define CBK   2048     // codebook size
#define BD    (BB*DD)  // 1048576
#define NB2   16       // CBK / 128 column blocks in GEMM2

// ---------------- scratch (device globals; no allocation allowed) ----------
__device__ float g_mean[BB * DD];      // 4 MB
__device__ float g_hidden[BB * HHID];  // 8 MB
__device__ float g_u[BB * DD];         // 4 MB
__device__ float g_cnorm[CBK];
__device__ float g_pval[BB * NB2];     // per-(row, colblock) min value
__device__ int   g_pidx[BB * NB2];     // per-(row, colblock) min index
__device__ int   g_argmin[BB];
__device__ float g_bsum[BB];           // per-block diff partials (deterministic)

// ---------------------------------------------------------------------------
// Kernel 1: masked gather + mean over history.  One block per batch row,
// 128 threads, each thread owns one float4 column of D=512.
// ---------------------------------------------------------------------------
__global__ void __launch_bounds__(128) gather_mean_kernel(
    const int* __restrict__ items, const float* __restrict__ item_embed)
{
    int b = blockIdx.x;
    int t = threadIdx.x;
    __shared__ int sidx[KHIST];
    for (int i = t; i < KHIST; i += 128) sidx[i] = items[b * KHIST + i];
    __syncthreads();

    const float4* E4 = (const float4*)item_embed;
    float4 acc = make_float4(0.f, 0.f, 0.f, 0.f);
    int cnt = 0;
    #pragma unroll 4
    for (int k = 0; k < KHIST; k++) {
        int idx = sidx[k];
        float m = (idx != 0) ? 1.0f : 0.0f;
        cnt += (idx != 0);
        float4 v = E4[(size_t)idx * 128 + t];
        acc.x += m * v.x; acc.y += m * v.y; acc.z += m * v.z; acc.w += m * v.w;
    }
    float inv = 1.0f / (float)cnt;
    float4 r = make_float4(acc.x * inv, acc.y * inv, acc.z * inv, acc.w * inv);
    ((float4*)g_mean)[b * 128 + t] = r;
}

// ---------------------------------------------------------------------------
// Kernel 2: codebook row squared norms.  One block per code, 128 threads.
// ---------------------------------------------------------------------------
__global__ void __launch_bounds__(128) cnorm_kernel(const float* __restrict__ codebook)
{
    int j = blockIdx.x;
    int t = threadIdx.x;
    float4 v = ((const float4*)codebook)[j * 128 + t];
    float s = v.x * v.x + v.y * v.y + v.z * v.z + v.w * v.w;
    #pragma unroll
    for (int o = 16; o > 0; o >>= 1) s += __shfl_down_sync(0xffffffffu, s, o);
    __shared__ float red[4];
    if ((t & 31) == 0) red[t >> 5] = s;
    __syncthreads();
    if (t == 0) g_cnorm[j] = red[0] + red[1] + red[2] + red[3];
}

// ---------------------------------------------------------------------------
// GEMM: BM=128 x BN tile, BK=16, 256 threads, 8 x (BN/16) register microtile,
// register-prefetch double buffering.
// WHICH=0: g_hidden = relu(g_mean @ W1 + b1)   [2048 x 1024, K=512],  BN=128
// WHICH=1: g_u      = g_hidden @ W2 + b2       [2048 x 512,  K=1024], BN=64
//          also scalar-stores user_embed into d_out slice (4B-aligned only)
// WHICH=2: fused scores+argmin partials:
//          s = cnorm[n] - 2*(g_u @ codebook^T) [2048 x 2048, K=512],  BN=128
//          per-(row, colblock) (minval, minidx) -> g_pval/g_pidx
// ---------------------------------------------------------------------------
template<int WHICH>
__global__ void __launch_bounds__(256) gemm_kernel(
    const float* __restrict__ Bm,    // W1 / W2 / codebook
    const float* __restrict__ bias,  // b1 / b2 / unused
    float* __restrict__ out2,        // user_embed slice of d_out (WHICH==1)
    int N, int Kd)
{
    constexpr int BM  = 128;
    constexpr int BN  = (WHICH == 1) ? 64 : 128;
    constexpr int TNR = BN / 16;
    constexpr int BK  = 16;

    const float* __restrict__ A =
        (WHICH == 0) ? g_mean : (WHICH == 1) ? g_hidden : g_u;
    float* __restrict__ out =
        (WHICH == 0) ? g_hidden : (WHICH == 1) ? g_u : nullptr;

    __shared__ float As[BK][BM];
    __shared__ float Bs[BK][BN];

    const int tid = threadIdx.x;
    const int tx = tid & 15, ty = tid >> 4;
    const int bm = blockIdx.y * BM, bn = blockIdx.x * BN;

    // ---- A load mapping: thread loads 2 float4 along K (rows of [M,K]) ----
    const int am = tid & 127;
    const int ak = (tid >> 7) * 8;          // 0 or 8
    const float* Aptr = A + (size_t)(bm + am) * Kd + ak;

    // ---- B load mapping ----
    const float* Bptr;
    int bk_r = 0, bn_c = 0;
    if (WHICH == 2) {
        // codebook [N,K] row-major; same mapping as A (transpose on store)
        Bptr = Bm + (size_t)(bn + am) * Kd + ak;
    } else if (WHICH == 0) {
        bk_r = tid >> 5;            // 0..7  (+8 for second load)
        bn_c = (tid & 31) * 4;      // 0..124
        Bptr = Bm + (size_t)bk_r * N + bn + bn_c;
    } else {
        bk_r = tid >> 4;            // 0..15
        bn_c = (tid & 15) * 4;      // 0..60
        Bptr = Bm + (size_t)bk_r * N + bn + bn_c;
    }

    float4 ra0, ra1, rb0, rb1;

    auto prefetch = [&](int k0) {
        ra0 = *(const float4*)(Aptr + k0);
        ra1 = *(const float4*)(Aptr + k0 + 4);
        if (WHICH == 2) {
            rb0 = *(const float4*)(Bptr + k0);
            rb1 = *(const float4*)(Bptr + k0 + 4);
        } else if (WHICH == 0) {
            rb0 = *(const float4*)(Bptr + (size_t)k0 * N);
            rb1 = *(const float4*)(Bptr + (size_t)(k0 + 8) * N);
        } else {
            rb0 = *(const float4*)(Bptr + (size_t)k0 * N);
        }
    };

    auto store_smem = [&]() {
        As[ak + 0][am] = ra0.x; As[ak + 1][am] = ra0.y;
        As[ak + 2][am] = ra0.z; As[ak + 3][am] = ra0.w;
        As[ak + 4][am] = ra1.x; As[ak + 5][am] = ra1.y;
        As[ak + 6][am] = ra1.z; As[ak + 7][am] = ra1.w;
        if (WHICH == 2) {
            Bs[ak + 0][am] = rb0.x; Bs[ak + 1][am] = rb0.y;
            Bs[ak + 2][am] = rb0.z; Bs[ak + 3][am] = rb0.w;
            Bs[ak + 4][am] = rb1.x; Bs[ak + 5][am] = rb1.y;
            Bs[ak + 6][am] = rb1.z; Bs[ak + 7][am] = rb1.w;
        } else if (WHICH == 0) {
            *(float4*)&Bs[bk_r][bn_c]     = rb0;
            *(float4*)&Bs[bk_r + 8][bn_c] = rb1;
        } else {
            *(float4*)&Bs[bk_r][bn_c] = rb0;
        }
    };

    float acc[8][TNR] = {};

    auto compute = [&]() {
        #pragma unroll
        for (int kk = 0; kk < BK; kk++) {
            float a[8], b[TNR];
            *(float4*)&a[0] = *(const float4*)&As[kk][ty * 8];
            *(float4*)&a[4] = *(const float4*)&As[kk][ty * 8 + 4];
            #pragma unroll
            for (int j4 = 0; j4 < TNR; j4 += 4)
                *(float4*)&b[j4] = *(const float4*)&Bs[kk][tx * TNR + j4];
            #pragma unroll
            for (int i = 0; i < 8; i++)
                #pragma unroll
                for (int j = 0; j < TNR; j++)
                    acc[i][j] = fmaf(a[i], b[j], acc[i][j]);
        }
    };

    prefetch(0);
    store_smem();
    __syncthreads();
    for (int k0 = BK; k0 < Kd; k0 += BK) {
        prefetch(k0);
        compute();
        __syncthreads();
        store_smem();
        __syncthreads();
    }
    compute();

    // ---- epilogue ----
    if (WHICH == 2) {
        #pragma unroll
        for (int i = 0; i < 8; i++) {
            int row = bm + ty * 8 + i;
            float minv = 3.0e38f;
            int   minj = 0x7fffffff;
            #pragma unroll
            for (int j = 0; j < TNR; j++) {
                int col = bn + tx * TNR + j;
                float s = g_cnorm[col] - 2.0f * acc[i][j];
                if (s < minv) { minv = s; minj = col; }  // ascending col -> first occurrence
            }
            // reduce across the 16 lanes (tx=0..15) holding this row
            #pragma unroll
            for (int off = 8; off > 0; off >>= 1) {
                float ov = __shfl_down_sync(0xffffffffu, minv, off, 16);
                int   oj = __shfl_down_sync(0xffffffffu, minj, off, 16);
                if (ov < minv || (ov == minv && oj < minj)) { minv = ov; minj = oj; }
            }
            if (tx == 0) {
                g_pval[(size_t)row * NB2 + blockIdx.x] = minv;
                g_pidx[(size_t)row * NB2 + blockIdx.x] = minj;
            }
        }
    } else {
        #pragma unroll
        for (int i = 0; i < 8; i++) {
            int row = bm + ty * 8 + i;
            #pragma unroll
            for (int j4 = 0; j4 < TNR; j4 += 4) {
                int col = bn + tx * TNR + j4;
                float4 bv = *(const float4*)&bias[col];
                float4 v = make_float4(acc[i][j4 + 0] + bv.x, acc[i][j4 + 1] + bv.y,
                                       acc[i][j4 + 2] + bv.z, acc[i][j4 + 3] + bv.w);
                if (WHICH == 0) {
                    v.x = v.x > 0.f ? v.x : 0.f;
                    v.y = v.y > 0.f ? v.y : 0.f;
                    v.z = v.z > 0.f ? v.z : 0.f;
                    v.w = v.w > 0.f ? v.w : 0.f;
                    *(float4*)&out[(size_t)row * N + col] = v;
                } else {
                    *(float4*)&out[(size_t)row * N + col] = v;
                    out2[(size_t)row * N + col + 0] = v.x;   // misaligned dest: scalar
                    out2[(size_t)row * N + col + 1] = v.y;
                    out2[(size_t)row * N + col + 2] = v.z;
                    out2[(size_t)row * N + col + 3] = v.w;
                }
            }
        }
    }
}

// ---------------------------------------------------------------------------
// Kernel 4: final argmin over NB2 column-block partials per row.
// ---------------------------------------------------------------------------
__global__ void __launch_bounds__(256) argmin_final_kernel()
{
    int b = blockIdx.x * 256 + threadIdx.x;   // 2048 rows
    float best = 3.0e38f;
    int   bi   = 0x7fffffff;
    #pragma unroll
    for (int j = 0; j < NB2; j++) {
        float v = g_pval[(size_t)b * NB2 + j];
        int   i = g_pidx[(size_t)b * NB2 + j];
        if (v < best || (v == best && i < bi)) { best = v; bi = i; }
    }
    g_argmin[b] = bi;
}

// ---------------------------------------------------------------------------
// Kernel 5: epilogue. Per batch row: q = codebook[id]; quant = u + (q-u);
// pos/neg item gathers; per-block diff partial sum.
// ---------------------------------------------------------------------------
__global__ void __launch_bounds__(128) epilogue_kernel(
    const float* __restrict__ codebook, const float* __restrict__ item_embed,
    const int* __restrict__ pos, const int* __restrict__ neg,
    float* __restrict__ out_q, float* __restrict__ out_pos,
    float* __restrict__ out_neg)
{
    int b = blockIdx.x;
    int t = threadIdx.x;
    int id = g_argmin[b];

    float4 q = ((const float4*)codebook)[(size_t)id * 128 + t];
    float4 u = ((const float4*)g_u)[(size_t)b * 128 + t];
    float4 d = make_float4(q.x - u.x, q.y - u.y, q.z - u.z, q.w - u.w);
    float4 qu = make_float4(u.x + d.x, u.y + d.y, u.z + d.z, u.w + d.w);
    ((float4*)out_q)[(size_t)b * 128 + t] = qu;

    int p = pos[b], n = neg[b];
    ((float4*)out_pos)[(size_t)b * 128 + t] = ((const float4*)item_embed)[(size_t)p * 128 + t];
    ((float4*)out_neg)[(size_t)b * 128 + t] = ((const float4*)item_embed)[(size_t)n * 128 + t];

    float ds = d.x * d.x + d.y * d.y + d.z * d.z + d.w * d.w;
    #pragma unroll
    for (int o = 16; o > 0; o >>= 1) ds += __shfl_down_sync(0xffffffffu, ds, o);
    __shared__ float red[4];
    if ((t & 31) == 0) red[t >> 5] = ds;
    __syncthreads();
    if (t == 0) g_bsum[b] = red[0] + red[1] + red[2] + red[3];
}

// ---------------------------------------------------------------------------
// Kernel 6: deterministic final reduction of diff = mean((q-u)^2).
// ---------------------------------------------------------------------------
__global__ void __launch_bounds__(256) diff_kernel(float* __restrict__ out_diff)
{
    int t = threadIdx.x;
    float s = 0.f;
    #pragma unroll
    for (int i = 0; i < BB / 256; i++) s += g_bsum[t + i * 256];
    __shared__ float sv[256];
    sv[t] = s;
    __syncthreads();
    for (int o = 128; o > 0; o >>= 1) {
        if (t < o) sv[t] += sv[t + o];
        __syncthreads();
    }
    if (t == 0) *out_diff = sv[0] * (1.0f / (float)BD);
}

// ---------------------------------------------------------------------------
extern "C" void kernel_launch(void* const* d_in, const int* in_sizes, int n_in,
                              void* d_out, int out_size)
{
    // metadata order:
    // 0 user_id 1 interacted_items 2 pos 3 neg 4 item_embed
    // 5 W1 6 b1 7 W2 8 b2 9 codebook
    const int*   items      = (const int*)  d_in[1];
    const int*   pos        = (const int*)  d_in[2];
    const int*   neg        = (const int*)  d_in[3];
    const float* item_embed = (const float*)d_in[4];
    const float* W1         = (const float*)d_in[5];
    const float* b1         = (const float*)d_in[6];
    const float* W2         = (const float*)d_in[7];
    const float* b2         = (const float*)d_in[8];
    const float* codebook   = (const float*)d_in[9];

    float* out      = (float*)d_out;
    float* out_q    = out;                  // quant_user  [B,D]
    float* out_pos  = out + (size_t)BD;     // pos_item    [B,D]
    float* out_neg  = out + (size_t)2 * BD; // neg_item    [B,D]
    float* out_diff = out + (size_t)3 * BD;           // scalar
    float* out_ue   = out + (size_t)3 * BD + 1;       // user_embed [B,D]

    gather_mean_kernel<<<BB, 128>>>(items, item_embed);
    cnorm_kernel<<<CBK, 128>>>(codebook);

    gemm_kernel<0><<<dim3(HHID / 128, BB / 128), 256>>>(W1, b1, nullptr, HHID, DD);
    gemm_kernel<1><<<dim3(DD / 64,    BB / 128), 256>>>(W2, b2, out_ue,  DD,  HHID);
    gemm_kernel<2><<<dim3(CBK / 128,  BB / 128), 256>>>(codebook, nullptr, nullptr, CBK, DD);

    argmin_final_kernel<<<BB / 256, 256>>>();
    epilogue_kernel<<<BB, 128>>>(codebook, item_embed, pos, neg, out_q, out_pos, out_neg);
    diff_kernel<<<1, 256>>>(out_diff);
}

// round 3
// speedup vs baseline: 1.0648x; 1.0001x over previous
#include <cuda_runtime.h>
#include <cstdint>

// Problem constants
#define BB    2048     // batch
#define KHIST 200      // history length
#define DD    512      // latent dim
#define HHID  1024     // 2*D
#define CBK   2048     // codebook size
#define BD    (BB*DD)  // 1048576
#define NB2   16       // CBK / 128 column blocks in GEMM2

// ---------------- scratch (device globals; no allocation allowed) ----------
__device__ float g_mean[BB * DD];      // 4 MB
__device__ float g_hidden[BB * HHID];  // 8 MB
__device__ float g_u[BB * DD];         // 4 MB
__device__ float g_cnorm[CBK];
__device__ float g_pval[BB * NB2];     // per-(row, colblock) min value
__device__ int   g_pidx[BB * NB2];     // per-(row, colblock) min index
__device__ int   g_argmin[BB];
__device__ float g_bsum[BB];           // per-block diff partials (deterministic)

// ---------------------------------------------------------------------------
// Kernel 1: masked gather + mean over history.  One block per batch row,
// 128 threads, each thread owns one float4 column of D=512.
// ---------------------------------------------------------------------------
__global__ void __launch_bounds__(128) gather_mean_kernel(
    const int* __restrict__ items, const float* __restrict__ item_embed)
{
    int b = blockIdx.x;
    int t = threadIdx.x;
    __shared__ int sidx[KHIST];
    for (int i = t; i < KHIST; i += 128) sidx[i] = items[b * KHIST + i];
    __syncthreads();

    const float4* E4 = (const float4*)item_embed;
    float4 acc = make_float4(0.f, 0.f, 0.f, 0.f);
    int cnt = 0;
    #pragma unroll 4
    for (int k = 0; k < KHIST; k++) {
        int idx = sidx[k];
        float m = (idx != 0) ? 1.0f : 0.0f;
        cnt += (idx != 0);
        float4 v = E4[(size_t)idx * 128 + t];
        acc.x += m * v.x; acc.y += m * v.y; acc.z += m * v.z; acc.w += m * v.w;
    }
    float inv = 1.0f / (float)cnt;
    float4 r = make_float4(acc.x * inv, acc.y * inv, acc.z * inv, acc.w * inv);
    ((float4*)g_mean)[b * 128 + t] = r;
}

// ---------------------------------------------------------------------------
// Kernel 2: codebook row squared norms.  One block per code, 128 threads.
// ---------------------------------------------------------------------------
__global__ void __launch_bounds__(128) cnorm_kernel(const float* __restrict__ codebook)
{
    int j = blockIdx.x;
    int t = threadIdx.x;
    float4 v = ((const float4*)codebook)[j * 128 + t];
    float s = v.x * v.x + v.y * v.y + v.z * v.z + v.w * v.w;
    #pragma unroll
    for (int o = 16; o > 0; o >>= 1) s += __shfl_down_sync(0xffffffffu, s, o);
    __shared__ float red[4];
    if ((t & 31) == 0) red[t >> 5] = s;
    __syncthreads();
    if (t == 0) g_cnorm[j] = red[0] + red[1] + red[2] + red[3];
}

// ---------------------------------------------------------------------------
// GEMM: BM=128 x BN tile, BK=16, 256 threads, 8 x (BN/16) register microtile,
// register-prefetch double buffering.
// WHICH=0: g_hidden = relu(g_mean @ W1 + b1)   [2048 x 1024, K=512],  BN=128
// WHICH=1: g_u      = g_hidden @ W2 + b2       [2048 x 512,  K=1024], BN=64
//          also scalar-stores user_embed into d_out slice (4B-aligned only)
// WHICH=2: fused scores+argmin partials:
//          s = cnorm[n] - 2*(g_u @ codebook^T) [2048 x 2048, K=512],  BN=128
//          per-(row, colblock) (minval, minidx) -> g_pval/g_pidx
// ---------------------------------------------------------------------------
template<int WHICH>
__global__ void __launch_bounds__(256) gemm_kernel(
    const float* __restrict__ Bm,    // W1 / W2 / codebook
    const float* __restrict__ bias,  // b1 / b2 / unused
    float* __restrict__ out2,        // user_embed slice of d_out (WHICH==1)
    int N, int Kd)
{
    constexpr int BM  = 128;
    constexpr int BN  = (WHICH == 1) ? 64 : 128;
    constexpr int TNR = BN / 16;
    constexpr int BK  = 16;

    const float* __restrict__ A =
        (WHICH == 0) ? g_mean : (WHICH == 1) ? g_hidden : g_u;
    float* __restrict__ out =
        (WHICH == 0) ? g_hidden : (WHICH == 1) ? g_u : nullptr;

    __shared__ float As[BK][BM];
    __shared__ float Bs[BK][BN];

    const int tid = threadIdx.x;
    const int tx = tid & 15, ty = tid >> 4;
    const int bm = blockIdx.y * BM, bn = blockIdx.x * BN;

    // ---- A load mapping: thread loads 2 float4 along K (rows of [M,K]) ----
    const int am = tid & 127;
    const int ak = (tid >> 7) * 8;          // 0 or 8
    const float* Aptr = A + (size_t)(bm + am) * Kd + ak;

    // ---- B load mapping ----
    const float* Bptr;
    int bk_r = 0, bn_c = 0;
    if (WHICH == 2) {
        // codebook [N,K] row-major; same mapping as A (transpose on store)
        Bptr = Bm + (size_t)(bn + am) * Kd + ak;
    } else if (WHICH == 0) {
        bk_r = tid >> 5;            // 0..7  (+8 for second load)
        bn_c = (tid & 31) * 4;      // 0..124
        Bptr = Bm + (size_t)bk_r * N + bn + bn_c;
    } else {
        bk_r = tid >> 4;            // 0..15
        bn_c = (tid & 15) * 4;      // 0..60
        Bptr = Bm + (size_t)bk_r * N + bn + bn_c;
    }

    float4 ra0, ra1, rb0, rb1;

    auto prefetch = [&](int k0) {
        ra0 = *(const float4*)(Aptr + k0);
        ra1 = *(const float4*)(Aptr + k0 + 4);
        if (WHICH == 2) {
            rb0 = *(const float4*)(Bptr + k0);
            rb1 = *(const float4*)(Bptr + k0 + 4);
        } else if (WHICH == 0) {
            rb0 = *(const float4*)(Bptr + (size_t)k0 * N);
            rb1 = *(const float4*)(Bptr + (size_t)(k0 + 8) * N);
        } else {
            rb0 = *(const float4*)(Bptr + (size_t)k0 * N);
        }
    };

    auto store_smem = [&]() {
        As[ak + 0][am] = ra0.x; As[ak + 1][am] = ra0.y;
        As[ak + 2][am] = ra0.z; As[ak + 3][am] = ra0.w;
        As[ak + 4][am] = ra1.x; As[ak + 5][am] = ra1.y;
        As[ak + 6][am] = ra1.z; As[ak + 7][am] = ra1.w;
        if (WHICH == 2) {
            Bs[ak + 0][am] = rb0.x; Bs[ak + 1][am] = rb0.y;
            Bs[ak + 2][am] = rb0.z; Bs[ak + 3][am] = rb0.w;
            Bs[ak + 4][am] = rb1.x; Bs[ak + 5][am] = rb1.y;
            Bs[ak + 6][am] = rb1.z; Bs[ak + 7][am] = rb1.w;
        } else if (WHICH == 0) {
            *(float4*)&Bs[bk_r][bn_c]     = rb0;
            *(float4*)&Bs[bk_r + 8][bn_c] = rb1;
        } else {
            *(float4*)&Bs[bk_r][bn_c] = rb0;
        }
    };

    float acc[8][TNR] = {};

    auto compute = [&]() {
        #pragma unroll
        for (int kk = 0; kk < BK; kk++) {
            float a[8], b[TNR];
            *(float4*)&a[0] = *(const float4*)&As[kk][ty * 8];
            *(float4*)&a[4] = *(const float4*)&As[kk][ty * 8 + 4];
            #pragma unroll
            for (int j4 = 0; j4 < TNR; j4 += 4)
                *(float4*)&b[j4] = *(const float4*)&Bs[kk][tx * TNR + j4];
            #pragma unroll
            for (int i = 0; i < 8; i++)
                #pragma unroll
                for (int j = 0; j < TNR; j++)
                    acc[i][j] = fmaf(a[i], b[j], acc[i][j]);
        }
    };

    prefetch(0);
    store_smem();
    __syncthreads();
    for (int k0 = BK; k0 < Kd; k0 += BK) {
        prefetch(k0);
        compute();
        __syncthreads();
        store_smem();
        __syncthreads();
    }
    compute();

    // ---- epilogue ----
    if (WHICH == 2) {
        #pragma unroll
        for (int i = 0; i < 8; i++) {
            int row = bm + ty * 8 + i;
            float minv = 3.0e38f;
            int   minj = 0x7fffffff;
            #pragma unroll
            for (int j = 0; j < TNR; j++) {
                int col = bn + tx * TNR + j;
                float s = g_cnorm[col] - 2.0f * acc[i][j];
                if (s < minv) { minv = s; minj = col; }  // ascending col -> first occurrence
            }
            // reduce across the 16 lanes (tx=0..15) holding this row
            #pragma unroll
            for (int off = 8; off > 0; off >>= 1) {
                float ov = __shfl_down_sync(0xffffffffu, minv, off, 16);
                int   oj = __shfl_down_sync(0xffffffffu, minj, off, 16);
                if (ov < minv || (ov == minv && oj < minj)) { minv = ov; minj = oj; }
            }
            if (tx == 0) {
                g_pval[(size_t)row * NB2 + blockIdx.x] = minv;
                g_pidx[(size_t)row * NB2 + blockIdx.x] = minj;
            }
        }
    } else {
        #pragma unroll
        for (int i = 0; i < 8; i++) {
            int row = bm + ty * 8 + i;
            #pragma unroll
            for (int j4 = 0; j4 < TNR; j4 += 4) {
                int col = bn + tx * TNR + j4;
                float4 bv = *(const float4*)&bias[col];
                float4 v = make_float4(acc[i][j4 + 0] + bv.x, acc[i][j4 + 1] + bv.y,
                                       acc[i][j4 + 2] + bv.z, acc[i][j4 + 3] + bv.w);
                if (WHICH == 0) {
                    v.x = v.x > 0.f ? v.x : 0.f;
                    v.y = v.y > 0.f ? v.y : 0.f;
                    v.z = v.z > 0.f ? v.z : 0.f;
                    v.w = v.w > 0.f ? v.w : 0.f;
                    *(float4*)&out[(size_t)row * N + col] = v;
                } else {
                    *(float4*)&out[(size_t)row * N + col] = v;
                    out2[(size_t)row * N + col + 0] = v.x;   // misaligned dest: scalar
                    out2[(size_t)row * N + col + 1] = v.y;
                    out2[(size_t)row * N + col + 2] = v.z;
                    out2[(size_t)row * N + col + 3] = v.w;
                }
            }
        }
    }
}

// ---------------------------------------------------------------------------
// Kernel 4: final argmin over NB2 column-block partials per row.
// ---------------------------------------------------------------------------
__global__ void __launch_bounds__(256) argmin_final_kernel()
{
    int b = blockIdx.x * 256 + threadIdx.x;   // 2048 rows
    float best = 3.0e38f;
    int   bi   = 0x7fffffff;
    #pragma unroll
    for (int j = 0; j < NB2; j++) {
        float v = g_pval[(size_t)b * NB2 + j];
        int   i = g_pidx[(size_t)b * NB2 + j];
        if (v < best || (v == best && i < bi)) { best = v; bi = i; }
    }
    g_argmin[b] = bi;
}

// ---------------------------------------------------------------------------
// Kernel 5: epilogue. Per batch row: q = codebook[id]; quant = u + (q-u);
// pos/neg item gathers; per-block diff partial sum.
// ---------------------------------------------------------------------------
__global__ void __launch_bounds__(128) epilogue_kernel(
    const float* __restrict__ codebook, const float* __restrict__ item_embed,
    const int* __restrict__ pos, const int* __restrict__ neg,
    float* __restrict__ out_q, float* __restrict__ out_pos,
    float* __restrict__ out_neg)
{
    int b = blockIdx.x;
    int t = threadIdx.x;
    int id = g_argmin[b];

    float4 q = ((const float4*)codebook)[(size_t)id * 128 + t];
    float4 u = ((const float4*)g_u)[(size_t)b * 128 + t];
    float4 d = make_float4(q.x - u.x, q.y - u.y, q.z - u.z, q.w - u.w);
    float4 qu = make_float4(u.x + d.x, u.y + d.y, u.z + d.z, u.w + d.w);
    ((float4*)out_q)[(size_t)b * 128 + t] = qu;

    int p = pos[b], n = neg[b];
    ((float4*)out_pos)[(size_t)b * 128 + t] = ((const float4*)item_embed)[(size_t)p * 128 + t];
    ((float4*)out_neg)[(size_t)b * 128 + t] = ((const float4*)item_embed)[(size_t)n * 128 + t];

    float ds = d.x * d.x + d.y * d.y + d.z * d.z + d.w * d.w;
    #pragma unroll
    for (int o = 16; o > 0; o >>= 1) ds += __shfl_down_sync(0xffffffffu, ds, o);
    __shared__ float red[4];
    if ((t & 31) == 0) red[t >> 5] = ds;
    __syncthreads();
    if (t == 0) g_bsum[b] = red[0] + red[1] + red[2] + red[3];
}

// ---------------------------------------------------------------------------
// Kernel 6: deterministic final reduction of diff = mean((q-u)^2).
// ---------------------------------------------------------------------------
__global__ void __launch_bounds__(256) diff_kernel(float* __restrict__ out_diff)
{
    int t = threadIdx.x;
    float s = 0.f;
    #pragma unroll
    for (int i = 0; i < BB / 256; i++) s += g_bsum[t + i * 256];
    __shared__ float sv[256];
    sv[t] = s;
    __syncthreads();
    for (int o = 128; o > 0; o >>= 1) {
        if (t < o) sv[t] += sv[t + o];
        __syncthreads();
    }
    if (t == 0) *out_diff = sv[0] * (1.0f / (float)BD);
}

// ---------------------------------------------------------------------------
extern "C" void kernel_launch(void* const* d_in, const int* in_sizes, int n_in,
                              void* d_out, int out_size)
{
    // metadata order:
    // 0 user_id 1 interacted_items 2 pos 3 neg 4 item_embed
    // 5 W1 6 b1 7 W2 8 b2 9 codebook
    const int*   items      = (const int*)  d_in[1];
    const int*   pos        = (const int*)  d_in[2];
    const int*   neg        = (const int*)  d_in[3];
    const float* item_embed = (const float*)d_in[4];
    const float* W1         = (const float*)d_in[5];
    const float* b1         = (const float*)d_in[6];
    const float* W2         = (const float*)d_in[7];
    const float* b2         = (const float*)d_in[8];
    const float* codebook   = (const float*)d_in[9];

    float* out      = (float*)d_out;
    float* out_q    = out;                  // quant_user  [B,D]
    float* out_pos  = out + (size_t)BD;     // pos_item    [B,D]
    float* out_neg  = out + (size_t)2 * BD; // neg_item    [B,D]
    float* out_diff = out + (size_t)3 * BD;           // scalar
    float* out_ue   = out + (size_t)3 * BD + 1;       // user_embed [B,D]

    gather_mean_kernel<<<BB, 128>>>(items, item_embed);
    cnorm_kernel<<<CBK, 128>>>(codebook);

    gemm_kernel<0><<<dim3(HHID / 128, BB / 128), 256>>>(W1, b1, nullptr, HHID, DD);
    gemm_kernel<1><<<dim3(DD / 64,    BB / 128), 256>>>(W2, b2, out_ue,  DD,  HHID);
    gemm_kernel<2><<<dim3(CBK / 128,  BB / 128), 256>>>(codebook, nullptr, nullptr, CBK, DD);

    argmin_final_kernel<<<BB / 256, 256>>>();
    epilogue_kernel<<<BB, 128>>>(codebook, item_embed, pos, neg, out_q, out_pos, out_neg);
    diff_kernel<<<1, 256>>>(out_diff);
}

// round 5
// speedup vs baseline: 1.9852x; 1.8644x over previous
#include <cuda_runtime.h>
#include <cuda_bf16.h>
#include <cstdint>

// Problem constants
#define BB    2048     // batch
#define KHIST 200      // history length
#define DD    512      // latent dim
#define HHID  1024     // 2*D
#define CBK   2048     // codebook size
#define BD    (BB*DD)  // 1048576
#define NBW   64       // CBK / 32 argmin partial chunks per row

// ---------------- scratch (device globals; no allocation allowed) ----------
__device__ float        g_u[BB * DD];
__device__ float        g_cnorm[CBK];
__device__ float        g_pval[BB * NBW];
__device__ int          g_pidx[BB * NBW];
__device__ int          g_argmin[BB];
__device__ float        g_bsum[BB];

// bf16 hi/lo split operands
__device__ __nv_bfloat16 g_meanH[BB * DD],   g_meanL[BB * DD];     // [2048,512]
__device__ __nv_bfloat16 g_hidH [BB * HHID], g_hidL [BB * HHID];   // [2048,1024]
__device__ __nv_bfloat16 g_uH   [BB * DD],   g_uL   [BB * DD];     // [2048,512]
__device__ __nv_bfloat16 g_W1tH [HHID * DD], g_W1tL [HHID * DD];   // [1024,512] (=W1^T)
__device__ __nv_bfloat16 g_W2tH [DD * HHID], g_W2tL [DD * HHID];   // [512,1024] (=W2^T)
__device__ __nv_bfloat16 g_cbH  [CBK * DD],  g_cbL  [CBK * DD];    // [2048,512]

// ---------------------------------------------------------------------------
// Portable PTX helpers (sm_80+; no tcgen05 — ptxas here targets plain sm_103)
// ---------------------------------------------------------------------------
__device__ __forceinline__ uint32_t smem_u32(const void* p) {
    uint32_t a;
    asm("{ .reg .u64 t; cvta.to.shared.u64 t, %1; cvt.u32.u64 %0, t; }" : "=r"(a) : "l"(p));
    return a;
}

#define CP_ASYNC16(dst, src) \
    asm volatile("cp.async.cg.shared.global [%0], [%1], 16;" :: "r"(dst), "l"(src))
#define CP_COMMIT() asm volatile("cp.async.commit_group;" ::: "memory")
#define CP_WAIT0()  asm volatile("cp.async.wait_group 0;" ::: "memory")
#define CP_WAIT1()  asm volatile("cp.async.wait_group 1;" ::: "memory")

__device__ __forceinline__ void ldsm4(uint32_t (&r)[4], uint32_t addr) {
    asm volatile("ldmatrix.sync.aligned.m8n8.x4.shared.b16 {%0,%1,%2,%3}, [%4];"
                 : "=r"(r[0]), "=r"(r[1]), "=r"(r[2]), "=r"(r[3]) : "r"(addr));
}

__device__ __forceinline__ void mma16816(float (&d)[4], const uint32_t (&a)[4],
                                         uint32_t b0, uint32_t b1) {
    asm volatile(
        "mma.sync.aligned.m16n8k16.row.col.f32.bf16.bf16.f32 "
        "{%0,%1,%2,%3}, {%4,%5,%6,%7}, {%8,%9}, {%0,%1,%2,%3};"
        : "+f"(d[0]), "+f"(d[1]), "+f"(d[2]), "+f"(d[3])
        : "r"(a[0]), "r"(a[1]), "r"(a[2]), "r"(a[3]), "r"(b0), "r"(b1));
}

__device__ __forceinline__ void split_bf16(float v, __nv_bfloat16& h, __nv_bfloat16& l) {
    h = __float2bfloat16(v);
    l = __float2bfloat16(v - __bfloat162float(h));
}

// ---------------------------------------------------------------------------
// Kernel 1: masked gather + mean; writes mean directly as bf16 hi/lo.
// ---------------------------------------------------------------------------
__global__ void __launch_bounds__(128) gather_mean_kernel(
    const int* __restrict__ items, const float* __restrict__ item_embed)
{
    int b = blockIdx.x;
    int t = threadIdx.x;
    __shared__ int sidx[KHIST];
    for (int i = t; i < KHIST; i += 128) sidx[i] = items[b * KHIST + i];
    __syncthreads();

    const float4* E4 = (const float4*)item_embed;
    float4 acc = make_float4(0.f, 0.f, 0.f, 0.f);
    int cnt = 0;
    #pragma unroll 4
    for (int k = 0; k < KHIST; k++) {
        int idx = sidx[k];
        float m = (idx != 0) ? 1.0f : 0.0f;
        cnt += (idx != 0);
        float4 v = E4[(size_t)idx * 128 + t];
        acc.x += m * v.x; acc.y += m * v.y; acc.z += m * v.z; acc.w += m * v.w;
    }
    float inv = 1.0f / (float)cnt;
    float vals[4] = {acc.x * inv, acc.y * inv, acc.z * inv, acc.w * inv};
    size_t base = (size_t)b * DD + t * 4;
    __nv_bfloat16 h[4], l[4];
    #pragma unroll
    for (int i = 0; i < 4; i++) split_bf16(vals[i], h[i], l[i]);
    *(__nv_bfloat162*)&g_meanH[base]     = {h[0], h[1]};
    *(__nv_bfloat162*)&g_meanH[base + 2] = {h[2], h[3]};
    *(__nv_bfloat162*)&g_meanL[base]     = {l[0], l[1]};
    *(__nv_bfloat162*)&g_meanL[base + 2] = {l[2], l[3]};
}

// ---------------------------------------------------------------------------
// Kernel 2: codebook norms + bf16 hi/lo split (fused).
// ---------------------------------------------------------------------------
__global__ void __launch_bounds__(128) cnorm_cb_kernel(const float* __restrict__ codebook)
{
    int j = blockIdx.x;
    int t = threadIdx.x;
    float4 v = ((const float4*)codebook)[j * 128 + t];
    float vals[4] = {v.x, v.y, v.z, v.w};
    size_t base = (size_t)j * DD + t * 4;
    __nv_bfloat16 h[4], l[4];
    #pragma unroll
    for (int i = 0; i < 4; i++) split_bf16(vals[i], h[i], l[i]);
    *(__nv_bfloat162*)&g_cbH[base]     = {h[0], h[1]};
    *(__nv_bfloat162*)&g_cbH[base + 2] = {h[2], h[3]};
    *(__nv_bfloat162*)&g_cbL[base]     = {l[0], l[1]};
    *(__nv_bfloat162*)&g_cbL[base + 2] = {l[2], l[3]};

    float s = v.x * v.x + v.y * v.y + v.z * v.z + v.w * v.w;
    #pragma unroll
    for (int o = 16; o > 0; o >>= 1) s += __shfl_down_sync(0xffffffffu, s, o);
    __shared__ float red[4];
    if ((t & 31) == 0) red[t >> 5] = s;
    __syncthreads();
    if (t == 0) g_cnorm[j] = red[0] + red[1] + red[2] + red[3];
}

// ---------------------------------------------------------------------------
// Kernel 3: weight transpose + bf16 split.  W [KD,ND] -> Wt [ND,KD] hi/lo.
// ---------------------------------------------------------------------------
__global__ void __launch_bounds__(256) wt_convert_kernel(
    const float* __restrict__ W, __nv_bfloat16* __restrict__ WtH,
    __nv_bfloat16* __restrict__ WtL, int KD, int ND)
{
    __shared__ float ts[32][33];
    int n0 = blockIdx.x * 32, k0 = blockIdx.y * 32;
    int tx = threadIdx.x, ty = threadIdx.y;
    #pragma unroll
    for (int i = ty; i < 32; i += 8)
        ts[i][tx] = W[(size_t)(k0 + i) * ND + n0 + tx];   // ts[k][n]
    __syncthreads();
    #pragma unroll
    for (int i = ty; i < 32; i += 8) {
        float v = ts[tx][i];                               // W[k0+tx][n0+i]
        __nv_bfloat16 h, l;
        split_bf16(v, h, l);
        size_t o = (size_t)(n0 + i) * KD + k0 + tx;
        WtH[o] = h;
        WtL[o] = l;
    }
}

// ---------------------------------------------------------------------------
// Tensor-core GEMM (mma.sync bf16x3, fp32 accum): C = A[M,Kd] @ B[N,Kd]^T
// 128 x BN CTA tile, K-chunks of 64 halves, SW128-swizzled smem, cp.async
// double buffering, ldmatrix feeds, register accumulators.
// WHICH=0: hid = relu(mean @ W1t^T + b1)  BN=128 -> g_hidH/L
// WHICH=1: u   = hid @ W2t^T + b2         BN=64  -> g_u, out_ue, g_uH/L
// WHICH=2: fused scores+argmin partials   BN=128 -> g_pval/g_pidx
// ---------------------------------------------------------------------------
template<int WHICH>
__global__ void __launch_bounds__(256) gemm_mma(
    const __nv_bfloat16* __restrict__ Ah, const __nv_bfloat16* __restrict__ Al,
    const __nv_bfloat16* __restrict__ Bh, const __nv_bfloat16* __restrict__ Bl,
    const float* __restrict__ bias, float* __restrict__ out_ue,
    int N, int Kd)
{
    constexpr int BM  = 128;
    constexpr int BN  = (WHICH == 1) ? 64 : 128;
    constexpr int WGN = BN / 32;          // warps along N
    constexpr int WGM = 8 / WGN;          // warps along M
    constexpr int WM  = BM / WGM;         // 64 or 32
    constexpr int MT  = WM / 16;          // 4 or 2
    constexpr int STAGE = 2 * (BM + BN) * 128;   // bytes per pipeline stage

    extern __shared__ char smem[];
    const uint32_t sbase = smem_u32(smem);
    const int tid  = threadIdx.x;
    const int lane = tid & 31;
    const int w    = tid >> 5;
    const int warp_m0 = (w / WGN) * WM;
    const int warp_n0 = (w % WGN) * 32;
    const int bm = blockIdx.y * BM, bn = blockIdx.x * BN;

    // ---- gmem -> smem stage loader (cp.async, SW128 swizzle) ----
    auto loadT = [&](const __nv_bfloat16* __restrict__ src, int row0, int k0,
                     uint32_t dst, int R) {
        #pragma unroll 4
        for (int i = 0; i < R * 8; i += 256) {
            int u = tid + i;
            int r = u >> 3, c8 = u & 7;
            uint32_t sd = dst + r * 128 + ((c8 * 16) ^ ((r & 7) << 4));
            const __nv_bfloat16* gs = src + (size_t)(row0 + r) * Kd + k0 + c8 * 8;
            CP_ASYNC16(sd, gs);
        }
    };
    auto issue = [&](int c, int buf) {
        uint32_t sb = sbase + (uint32_t)buf * STAGE;
        int k0 = c * 64;
        loadT(Ah, bm, k0, sb, BM);
        loadT(Al, bm, k0, sb + BM * 128, BM);
        loadT(Bh, bn, k0, sb + 2 * BM * 128, BN);
        loadT(Bl, bn, k0, sb + 2 * BM * 128 + BN * 128, BN);
    };

    // ---- per-lane ldmatrix address components ----
    const int tile = lane >> 3, lr = lane & 7;
    const uint32_t xorp = (uint32_t)(lr << 4);
    const int aRow = warp_m0 + ((tile & 1) << 3) + lr;   // A: t0=(m0,k0) t1=(m8,k0) t2=(m0,k8) t3=(m8,k8)
    const uint32_t aK = (uint32_t)((tile >> 1) << 4);
    const int bRow = warp_n0 + ((tile >> 1) << 3) + lr;  // B: t0=(n0,k0) t1=(n0,k8) t2=(n8,k0) t3=(n8,k8)
    const uint32_t bK = (uint32_t)((tile & 1) << 4);

    float acc[MT][4][4] = {};

    const int NC = Kd / 64;
    issue(0, 0); CP_COMMIT();
    issue(1, 1); CP_COMMIT();
    CP_WAIT1();
    __syncthreads();

    for (int c = 0; c < NC; c++) {
        // ---- compute chunk c from buffer c&1 ----
        uint32_t s0 = sbase + (uint32_t)(c & 1) * STAGE;
        uint32_t pA[2] = { s0, s0 + BM * 128 };
        uint32_t pB[2] = { s0 + 2 * BM * 128, s0 + 2 * BM * 128 + BN * 128 };

        #pragma unroll
        for (int kk = 0; kk < 4; kk++) {
            uint32_t akb = (((uint32_t)kk << 5) + aK) ^ xorp;
            uint32_t bkb = (((uint32_t)kk << 5) + bK) ^ xorp;
            uint32_t a[2][MT][4];
            uint32_t b[2][4][2];
            #pragma unroll
            for (int s = 0; s < 2; s++)
                #pragma unroll
                for (int mt = 0; mt < MT; mt++)
                    ldsm4(a[s][mt], pA[s] + (uint32_t)(aRow + mt * 16) * 128 + akb);
            #pragma unroll
            for (int s = 0; s < 2; s++)
                #pragma unroll
                for (int ng = 0; ng < 2; ng++) {
                    uint32_t t4[4];
                    ldsm4(t4, pB[s] + (uint32_t)(bRow + ng * 16) * 128 + bkb);
                    b[s][2 * ng][0] = t4[0]; b[s][2 * ng][1] = t4[1];
                    b[s][2 * ng + 1][0] = t4[2]; b[s][2 * ng + 1][1] = t4[3];
                }
            #pragma unroll
            for (int mt = 0; mt < MT; mt++)
                #pragma unroll
                for (int nt = 0; nt < 4; nt++)
                    mma16816(acc[mt][nt], a[0][mt], b[0][nt][0], b[0][nt][1]);
            #pragma unroll
            for (int mt = 0; mt < MT; mt++)
                #pragma unroll
                for (int nt = 0; nt < 4; nt++)
                    mma16816(acc[mt][nt], a[0][mt], b[1][nt][0], b[1][nt][1]);
            #pragma unroll
            for (int mt = 0; mt < MT; mt++)
                #pragma unroll
                for (int nt = 0; nt < 4; nt++)
                    mma16816(acc[mt][nt], a[1][mt], b[0][nt][0], b[0][nt][1]);
        }

        if (c == NC - 1) break;
        __syncthreads();                    // everyone done reading buf c&1
        if (c + 2 < NC) { issue(c + 2, c & 1); CP_COMMIT(); CP_WAIT1(); }
        else            { CP_WAIT0(); }
        __syncthreads();
    }

    // ---------------- epilogue (registers -> gmem) ----------------
    const int lr4 = lane >> 2;          // 0..7
    const int lc2 = (lane & 3) * 2;     // 0,2,4,6

    if (WHICH == 2) {
        int chunk = (bn + warp_n0) >> 5;
        #pragma unroll
        for (int mt = 0; mt < MT; mt++)
            #pragma unroll
            for (int half = 0; half < 2; half++) {
                int row = bm + warp_m0 + mt * 16 + lr4 + half * 8;
                float mv = 3.0e38f; int mj = 0x7fffffff;
                #pragma unroll
                for (int nt = 0; nt < 4; nt++) {
                    int col = bn + warp_n0 + nt * 8 + lc2;
                    float2 cn = *(const float2*)&g_cnorm[col];
                    float s0 = cn.x - 2.0f * acc[mt][nt][half * 2 + 0];
                    float s1 = cn.y - 2.0f * acc[mt][nt][half * 2 + 1];
                    if (s0 < mv) { mv = s0; mj = col; }
                    if (s1 < mv) { mv = s1; mj = col + 1; }
                }
                #pragma unroll
                for (int o = 1; o < 4; o <<= 1) {
                    float ov = __shfl_xor_sync(0xffffffffu, mv, o);
                    int   oj = __shfl_xor_sync(0xffffffffu, mj, o);
                    if (ov < mv || (ov == mv && oj < mj)) { mv = ov; mj = oj; }
                }
                if ((lane & 3) == 0) {
                    g_pval[(size_t)row * NBW + chunk] = mv;
                    g_pidx[(size_t)row * NBW + chunk] = mj;
                }
            }
    } else {
        #pragma unroll
        for (int mt = 0; mt < MT; mt++)
            #pragma unroll
            for (int half = 0; half < 2; half++) {
                int row = bm + warp_m0 + mt * 16 + lr4 + half * 8;
                #pragma unroll
                for (int nt = 0; nt < 4; nt++) {
                    int col = bn + warp_n0 + nt * 8 + lc2;
                    float2 bv = *(const float2*)&bias[col];
                    float v0 = acc[mt][nt][half * 2 + 0] + bv.x;
                    float v1 = acc[mt][nt][half * 2 + 1] + bv.y;
                    size_t o = (size_t)row * N + col;
                    if (WHICH == 0) {
                        v0 = fmaxf(v0, 0.f); v1 = fmaxf(v1, 0.f);
                        __nv_bfloat16 h0, l0, h1, l1;
                        split_bf16(v0, h0, l0); split_bf16(v1, h1, l1);
                        *(__nv_bfloat162*)&g_hidH[o] = {h0, h1};
                        *(__nv_bfloat162*)&g_hidL[o] = {l0, l1};
                    } else {
                        *(float2*)&g_u[o] = make_float2(v0, v1);
                        out_ue[o] = v0; out_ue[o + 1] = v1;
                        __nv_bfloat16 h0, l0, h1, l1;
                        split_bf16(v0, h0, l0); split_bf16(v1, h1, l1);
                        *(__nv_bfloat162*)&g_uH[o] = {h0, h1};
                        *(__nv_bfloat162*)&g_uL[o] = {l0, l1};
                    }
                }
            }
    }
}

// ---------------------------------------------------------------------------
// Final argmin over NBW column-chunk partials per row.
// ---------------------------------------------------------------------------
__global__ void __launch_bounds__(256) argmin_final_kernel()
{
    int b = blockIdx.x * 256 + threadIdx.x;
    float best = 3.0e38f;
    int   bi   = 0x7fffffff;
    #pragma unroll 8
    for (int j = 0; j < NBW; j++) {
        float v = g_pval[(size_t)b * NBW + j];
        int   i = g_pidx[(size_t)b * NBW + j];
        if (v < best || (v == best && i < bi)) { best = v; bi = i; }
    }
    g_argmin[b] = bi;
}

// ---------------------------------------------------------------------------
// Epilogue: q=codebook[id]; quant=u+(q-u); pos/neg gathers; diff partials.
// ---------------------------------------------------------------------------
__global__ void __launch_bounds__(128) epilogue_kernel(
    const float* __restrict__ codebook, const float* __restrict__ item_embed,
    const int* __restrict__ pos, const int* __restrict__ neg,
    float* __restrict__ out_q, float* __restrict__ out_pos,
    float* __restrict__ out_neg)
{
    int b = blockIdx.x;
    int t = threadIdx.x;
    int id = g_argmin[b];

    float4 q = ((const float4*)codebook)[(size_t)id * 128 + t];
    float4 u = ((const float4*)g_u)[(size_t)b * 128 + t];
    float4 d = make_float4(q.x - u.x, q.y - u.y, q.z - u.z, q.w - u.w);
    float4 qu = make_float4(u.x + d.x, u.y + d.y, u.z + d.z, u.w + d.w);
    ((float4*)out_q)[(size_t)b * 128 + t] = qu;

    int p = pos[b], n = neg[b];
    ((float4*)out_pos)[(size_t)b * 128 + t] = ((const float4*)item_embed)[(size_t)p * 128 + t];
    ((float4*)out_neg)[(size_t)b * 128 + t] = ((const float4*)item_embed)[(size_t)n * 128 + t];

    float ds = d.x * d.x + d.y * d.y + d.z * d.z + d.w * d.w;
    #pragma unroll
    for (int o = 16; o > 0; o >>= 1) ds += __shfl_down_sync(0xffffffffu, ds, o);
    __shared__ float red[4];
    if ((t & 31) == 0) red[t >> 5] = ds;
    __syncthreads();
    if (t == 0) g_bsum[b] = red[0] + red[1] + red[2] + red[3];
}

__global__ void __launch_bounds__(256) diff_kernel(float* __restrict__ out_diff)
{
    int t = threadIdx.x;
    float s = 0.f;
    #pragma unroll
    for (int i = 0; i < BB / 256; i++) s += g_bsum[t + i * 256];
    __shared__ float sv[256];
    sv[t] = s;
    __syncthreads();
    for (int o = 128; o > 0; o >>= 1) {
        if (t < o) sv[t] += sv[t + o];
        __syncthreads();
    }
    if (t == 0) *out_diff = sv[0] * (1.0f / (float)BD);
}

// ---------------------------------------------------------------------------
extern "C" void kernel_launch(void* const* d_in, const int* in_sizes, int n_in,
                              void* d_out, int out_size)
{
    const int*   items      = (const int*)  d_in[1];
    const int*   pos        = (const int*)  d_in[2];
    const int*   neg        = (const int*)  d_in[3];
    const float* item_embed = (const float*)d_in[4];
    const float* W1         = (const float*)d_in[5];
    const float* b1         = (const float*)d_in[6];
    const float* W2         = (const float*)d_in[7];
    const float* b2         = (const float*)d_in[8];
    const float* codebook   = (const float*)d_in[9];

    float* out      = (float*)d_out;
    float* out_q    = out;
    float* out_pos  = out + (size_t)BD;
    float* out_neg  = out + (size_t)2 * BD;
    float* out_diff = out + (size_t)3 * BD;
    float* out_ue   = out + (size_t)3 * BD + 1;

    const int SMEM_BIG   = 2 * 2 * (128 + 128) * 128;  // 131072
    const int SMEM_SMALL = 2 * 2 * (128 + 64) * 128;   //  98304
    cudaFuncSetAttribute(gemm_mma<0>, cudaFuncAttributeMaxDynamicSharedMemorySize, SMEM_BIG);
    cudaFuncSetAttribute(gemm_mma<1>, cudaFuncAttributeMaxDynamicSharedMemorySize, SMEM_SMALL);
    cudaFuncSetAttribute(gemm_mma<2>, cudaFuncAttributeMaxDynamicSharedMemorySize, SMEM_BIG);

    __nv_bfloat16 *meanH, *meanL, *hidH, *hidL, *uH, *uL, *w1tH, *w1tL, *w2tH, *w2tL, *cbH, *cbL;
    cudaGetSymbolAddress((void**)&meanH, g_meanH);
    cudaGetSymbolAddress((void**)&meanL, g_meanL);
    cudaGetSymbolAddress((void**)&hidH,  g_hidH);
    cudaGetSymbolAddress((void**)&hidL,  g_hidL);
    cudaGetSymbolAddress((void**)&uH,    g_uH);
    cudaGetSymbolAddress((void**)&uL,    g_uL);
    cudaGetSymbolAddress((void**)&w1tH,  g_W1tH);
    cudaGetSymbolAddress((void**)&w1tL,  g_W1tL);
    cudaGetSymbolAddress((void**)&w2tH,  g_W2tH);
    cudaGetSymbolAddress((void**)&w2tL,  g_W2tL);
    cudaGetSymbolAddress((void**)&cbH,   g_cbH);
    cudaGetSymbolAddress((void**)&cbL,   g_cbL);

    gather_mean_kernel<<<BB, 128>>>(items, item_embed);
    cnorm_cb_kernel<<<CBK, 128>>>(codebook);
    wt_convert_kernel<<<dim3(HHID / 32, DD / 32),  dim3(32, 8)>>>(W1, w1tH, w1tL, DD,   HHID);
    wt_convert_kernel<<<dim3(DD / 32,  HHID / 32), dim3(32, 8)>>>(W2, w2tH, w2tL, HHID, DD);

    gemm_mma<0><<<dim3(HHID / 128, BB / 128), 256, SMEM_BIG>>>(
        meanH, meanL, w1tH, w1tL, b1, nullptr, HHID, DD);
    gemm_mma<1><<<dim3(DD / 64,    BB / 128), 256, SMEM_SMALL>>>(
        hidH,  hidL,  w2tH, w2tL, b2, out_ue,  DD,  HHID);
    gemm_mma<2><<<dim3(CBK / 128,  BB / 128), 256, SMEM_BIG>>>(
        uH,    uL,    cbH,  cbL,  nullptr, nullptr, CBK, DD);

    argmin_final_kernel<<<BB / 256, 256>>>();
    epilogue_kernel<<<BB, 128>>>(codebook, item_embed, pos, neg, out_q, out_pos, out_neg);
    diff_kernel<<<1, 256>>>(out_diff);
}

// round 6
// speedup vs baseline: 2.2607x; 1.1388x over previous
#include <cuda_runtime.h>
#include <cuda_bf16.h>
#include <cstdint>

// Problem constants
#define BB    2048     // batch
#define KHIST 200      // history length
#define DD    512      // latent dim
#define HHID  1024     // 2*D
#define CBK   2048     // codebook size
#define BD    (BB*DD)  // 1048576
#define NBW   64       // CBK / 32 argmin partial chunks per row

// ---------------- scratch (device globals; no allocation allowed) ----------
__device__ float        g_u[BB * DD];
__device__ float        g_cnorm[CBK];
__device__ float        g_pval[BB * NBW];
__device__ int          g_pidx[BB * NBW];
__device__ float        g_bsum[BB];

// bf16 hi/lo split operands
__device__ __nv_bfloat16 g_meanH[BB * DD],   g_meanL[BB * DD];     // [2048,512]
__device__ __nv_bfloat16 g_hidH [BB * HHID], g_hidL [BB * HHID];   // [2048,1024]
__device__ __nv_bfloat16 g_uH   [BB * DD],   g_uL   [BB * DD];     // [2048,512]
__device__ __nv_bfloat16 g_W1tH [HHID * DD], g_W1tL [HHID * DD];   // [1024,512] (=W1^T)
__device__ __nv_bfloat16 g_W2tH [DD * HHID], g_W2tL [DD * HHID];   // [512,1024] (=W2^T)
__device__ __nv_bfloat16 g_cbH  [CBK * DD],  g_cbL  [CBK * DD];    // [2048,512]

// ---------------------------------------------------------------------------
// Portable PTX helpers (sm_80+; ptxas here targets plain sm_103 — no tcgen05)
// ---------------------------------------------------------------------------
__device__ __forceinline__ uint32_t smem_u32(const void* p) {
    uint32_t a;
    asm("{ .reg .u64 t; cvta.to.shared.u64 t, %1; cvt.u32.u64 %0, t; }" : "=r"(a) : "l"(p));
    return a;
}

#define CP_ASYNC16(dst, src) \
    asm volatile("cp.async.cg.shared.global [%0], [%1], 16;" :: "r"(dst), "l"(src))
#define CP_COMMIT() asm volatile("cp.async.commit_group;" ::: "memory")
#define CP_WAIT0()  asm volatile("cp.async.wait_group 0;" ::: "memory")
#define CP_WAIT1()  asm volatile("cp.async.wait_group 1;" ::: "memory")

__device__ __forceinline__ void ldsm4(uint32_t (&r)[4], uint32_t addr) {
    asm volatile("ldmatrix.sync.aligned.m8n8.x4.shared.b16 {%0,%1,%2,%3}, [%4];"
                 : "=r"(r[0]), "=r"(r[1]), "=r"(r[2]), "=r"(r[3]) : "r"(addr));
}

__device__ __forceinline__ void mma16816(float (&d)[4], const uint32_t (&a)[4],
                                         uint32_t b0, uint32_t b1) {
    asm volatile(
        "mma.sync.aligned.m16n8k16.row.col.f32.bf16.bf16.f32 "
        "{%0,%1,%2,%3}, {%4,%5,%6,%7}, {%8,%9}, {%0,%1,%2,%3};"
        : "+f"(d[0]), "+f"(d[1]), "+f"(d[2]), "+f"(d[3])
        : "r"(a[0]), "r"(a[1]), "r"(a[2]), "r"(a[3]), "r"(b0), "r"(b1));
}

__device__ __forceinline__ void split_bf16(float v, __nv_bfloat16& h, __nv_bfloat16& l) {
    h = __float2bfloat16(v);
    l = __float2bfloat16(v - __bfloat162float(h));
}

// ---------------------------------------------------------------------------
// Fused PREP megakernel (one launch; independent parts run concurrently):
//   blocks [0,2048)      : masked gather + mean -> g_meanH/L
//   blocks [2048,4096)   : codebook norms + hi/lo split
//   blocks [4096,4608)   : W1^T hi/lo split  (512 blocks)
//   blocks [4608,5120)   : W2^T hi/lo split  (512 blocks)
// 128 threads per block.
// ---------------------------------------------------------------------------
__global__ void __launch_bounds__(128) prep_kernel(
    const int* __restrict__ items, const float* __restrict__ item_embed,
    const float* __restrict__ codebook,
    const float* __restrict__ W1, const float* __restrict__ W2)
{
    __shared__ int   sidx[KHIST];
    __shared__ float ts[32][33];
    __shared__ float red[4];

    const int blk = blockIdx.x;
    const int t = threadIdx.x;

    if (blk < 2048) {
        // ----- gather + mean -----
        int b = blk;
        for (int i = t; i < KHIST; i += 128) sidx[i] = items[b * KHIST + i];
        __syncthreads();
        const float4* E4 = (const float4*)item_embed;
        float4 acc = make_float4(0.f, 0.f, 0.f, 0.f);
        int cnt = 0;
        #pragma unroll 4
        for (int k = 0; k < KHIST; k++) {
            int idx = sidx[k];
            float m = (idx != 0) ? 1.0f : 0.0f;
            cnt += (idx != 0);
            float4 v = E4[(size_t)idx * 128 + t];
            acc.x += m * v.x; acc.y += m * v.y; acc.z += m * v.z; acc.w += m * v.w;
        }
        float inv = 1.0f / (float)cnt;
        float vals[4] = {acc.x * inv, acc.y * inv, acc.z * inv, acc.w * inv};
        size_t base = (size_t)b * DD + t * 4;
        __nv_bfloat16 h[4], l[4];
        #pragma unroll
        for (int i = 0; i < 4; i++) split_bf16(vals[i], h[i], l[i]);
        *(__nv_bfloat162*)&g_meanH[base]     = {h[0], h[1]};
        *(__nv_bfloat162*)&g_meanH[base + 2] = {h[2], h[3]};
        *(__nv_bfloat162*)&g_meanL[base]     = {l[0], l[1]};
        *(__nv_bfloat162*)&g_meanL[base + 2] = {l[2], l[3]};
    } else if (blk < 4096) {
        // ----- codebook norm + split -----
        int j = blk - 2048;
        float4 v = ((const float4*)codebook)[j * 128 + t];
        float vals[4] = {v.x, v.y, v.z, v.w};
        size_t base = (size_t)j * DD + t * 4;
        __nv_bfloat16 h[4], l[4];
        #pragma unroll
        for (int i = 0; i < 4; i++) split_bf16(vals[i], h[i], l[i]);
        *(__nv_bfloat162*)&g_cbH[base]     = {h[0], h[1]};
        *(__nv_bfloat162*)&g_cbH[base + 2] = {h[2], h[3]};
        *(__nv_bfloat162*)&g_cbL[base]     = {l[0], l[1]};
        *(__nv_bfloat162*)&g_cbL[base + 2] = {l[2], l[3]};

        float s = v.x * v.x + v.y * v.y + v.z * v.z + v.w * v.w;
        #pragma unroll
        for (int o = 16; o > 0; o >>= 1) s += __shfl_down_sync(0xffffffffu, s, o);
        if ((t & 31) == 0) red[t >> 5] = s;
        __syncthreads();
        if (t == 0) g_cnorm[j] = red[0] + red[1] + red[2] + red[3];
    } else {
        // ----- weight transpose + split -----
        const float* W;
        __nv_bfloat16 *WtH, *WtL;
        int KD, ND, w;
        if (blk < 4608) {
            w = blk - 4096; W = W1; WtH = g_W1tH; WtL = g_W1tL; KD = DD; ND = HHID;
        } else {
            w = blk - 4608; W = W2; WtH = g_W2tH; WtL = g_W2tL; KD = HHID; ND = DD;
        }
        int nblk = ND / 32;
        int n0 = (w % nblk) * 32, k0 = (w / nblk) * 32;
        int tx = t & 31, ty = t >> 5;          // 32 x 4
        #pragma unroll
        for (int i = ty; i < 32; i += 4)
            ts[i][tx] = W[(size_t)(k0 + i) * ND + n0 + tx];   // ts[k][n]
        __syncthreads();
        #pragma unroll
        for (int i = ty; i < 32; i += 4) {
            float v = ts[tx][i];                               // W[k0+tx][n0+i]
            __nv_bfloat16 h, l;
            split_bf16(v, h, l);
            size_t o = (size_t)(n0 + i) * KD + k0 + tx;
            WtH[o] = h;
            WtL[o] = l;
        }
    }
}

// ---------------------------------------------------------------------------
// Tensor-core GEMM (mma.sync bf16x3, fp32 accum): C = A[M,Kd] @ B[N,Kd]^T
// 128 x BN CTA tile, K-chunks of 64 halves, SW128-swizzled smem, 3-stage
// cp.async pipeline, ldmatrix feeds, register accumulators.
// WHICH=0: hid = relu(mean @ W1t^T + b1)  BN=128 -> g_hidH/L
// WHICH=1: u   = hid @ W2t^T + b2         BN=64  -> g_u, out_ue, g_uH/L
// WHICH=2: fused scores+argmin partials   BN=128 -> g_pval/g_pidx
// ---------------------------------------------------------------------------
template<int WHICH>
__global__ void __launch_bounds__(256) gemm_mma(
    const __nv_bfloat16* __restrict__ Ah, const __nv_bfloat16* __restrict__ Al,
    const __nv_bfloat16* __restrict__ Bh, const __nv_bfloat16* __restrict__ Bl,
    const float* __restrict__ bias, float* __restrict__ out_ue,
    int N, int Kd)
{
    constexpr int BM  = 128;
    constexpr int BN  = (WHICH == 1) ? 64 : 128;
    constexpr int WGN = BN / 32;          // warps along N
    constexpr int WGM = 8 / WGN;          // warps along M
    constexpr int WM  = BM / WGM;         // 64 or 32
    constexpr int MT  = WM / 16;          // 4 or 2
    constexpr int STAGE = 2 * (BM + BN) * 128;   // bytes per pipeline stage

    extern __shared__ char smem[];
    const uint32_t sbase = smem_u32(smem);
    const int tid  = threadIdx.x;
    const int lane = tid & 31;
    const int w    = tid >> 5;
    const int warp_m0 = (w / WGN) * WM;
    const int warp_n0 = (w % WGN) * 32;
    const int bm = blockIdx.y * BM, bn = blockIdx.x * BN;

    // ---- gmem -> smem stage loader (cp.async, SW128 swizzle) ----
    auto loadT = [&](const __nv_bfloat16* __restrict__ src, int row0, int k0,
                     uint32_t dst, int R) {
        #pragma unroll 4
        for (int i = 0; i < R * 8; i += 256) {
            int u = tid + i;
            int r = u >> 3, c8 = u & 7;
            uint32_t sd = dst + r * 128 + ((c8 * 16) ^ ((r & 7) << 4));
            const __nv_bfloat16* gs = src + (size_t)(row0 + r) * Kd + k0 + c8 * 8;
            CP_ASYNC16(sd, gs);
        }
    };
    auto issue = [&](int c, int buf) {
        uint32_t sb = sbase + (uint32_t)buf * STAGE;
        int k0 = c * 64;
        loadT(Ah, bm, k0, sb, BM);
        loadT(Al, bm, k0, sb + BM * 128, BM);
        loadT(Bh, bn, k0, sb + 2 * BM * 128, BN);
        loadT(Bl, bn, k0, sb + 2 * BM * 128 + BN * 128, BN);
    };

    // ---- per-lane ldmatrix address components ----
    const int tile = lane >> 3, lr = lane & 7;
    const uint32_t xorp = (uint32_t)(lr << 4);
    const int aRow = warp_m0 + ((tile & 1) << 3) + lr;
    const uint32_t aK = (uint32_t)((tile >> 1) << 4);
    const int bRow = warp_n0 + ((tile >> 1) << 3) + lr;
    const uint32_t bK = (uint32_t)((tile & 1) << 4);

    float acc[MT][4][4] = {};

    const int NC = Kd / 64;
    issue(0, 0); CP_COMMIT();
    issue(1, 1); CP_COMMIT();
    CP_WAIT1();                 // chunk 0 resident
    __syncthreads();

    for (int c = 0; c < NC; c++) {
        int buf = c % 3;
        uint32_t s0 = sbase + (uint32_t)buf * STAGE;
        uint32_t pA[2] = { s0, s0 + BM * 128 };
        uint32_t pB[2] = { s0 + 2 * BM * 128, s0 + 2 * BM * 128 + BN * 128 };

        #pragma unroll
        for (int kk = 0; kk < 4; kk++) {
            uint32_t akb = (((uint32_t)kk << 5) + aK) ^ xorp;
            uint32_t bkb = (((uint32_t)kk << 5) + bK) ^ xorp;
            uint32_t a[2][MT][4];
            uint32_t b[2][4][2];
            #pragma unroll
            for (int s = 0; s < 2; s++)
                #pragma unroll
                for (int mt = 0; mt < MT; mt++)
                    ldsm4(a[s][mt], pA[s] + (uint32_t)(aRow + mt * 16) * 128 + akb);
            #pragma unroll
            for (int s = 0; s < 2; s++)
                #pragma unroll
                for (int ng = 0; ng < 2; ng++) {
                    uint32_t t4[4];
                    ldsm4(t4, pB[s] + (uint32_t)(bRow + ng * 16) * 128 + bkb);
                    b[s][2 * ng][0] = t4[0]; b[s][2 * ng][1] = t4[1];
                    b[s][2 * ng + 1][0] = t4[2]; b[s][2 * ng + 1][1] = t4[3];
                }
            #pragma unroll
            for (int mt = 0; mt < MT; mt++)
                #pragma unroll
                for (int nt = 0; nt < 4; nt++)
                    mma16816(acc[mt][nt], a[0][mt], b[0][nt][0], b[0][nt][1]);
            #pragma unroll
            for (int mt = 0; mt < MT; mt++)
                #pragma unroll
                for (int nt = 0; nt < 4; nt++)
                    mma16816(acc[mt][nt], a[0][mt], b[1][nt][0], b[1][nt][1]);
            #pragma unroll
            for (int mt = 0; mt < MT; mt++)
                #pragma unroll
                for (int nt = 0; nt < 4; nt++)
                    mma16816(acc[mt][nt], a[1][mt], b[0][nt][0], b[0][nt][1]);
        }

        if (c == NC - 1) break;
        __syncthreads();                       // all warps done reading buf (c+2)%3's old data
        if (c + 2 < NC) { issue(c + 2, (c + 2) % 3); CP_COMMIT(); CP_WAIT1(); }
        else            { CP_WAIT0(); }        // ensure chunk c+1 resident
        __syncthreads();
    }

    // ---------------- epilogue (registers -> gmem) ----------------
    const int lr4 = lane >> 2;          // 0..7
    const int lc2 = (lane & 3) * 2;     // 0,2,4,6

    if (WHICH == 2) {
        int chunk = (bn + warp_n0) >> 5;
        #pragma unroll
        for (int mt = 0; mt < MT; mt++)
            #pragma unroll
            for (int half = 0; half < 2; half++) {
                int row = bm + warp_m0 + mt * 16 + lr4 + half * 8;
                float mv = 3.0e38f; int mj = 0x7fffffff;
                #pragma unroll
                for (int nt = 0; nt < 4; nt++) {
                    int col = bn + warp_n0 + nt * 8 + lc2;
                    float2 cn = *(const float2*)&g_cnorm[col];
                    float s0 = cn.x - 2.0f * acc[mt][nt][half * 2 + 0];
                    float s1 = cn.y - 2.0f * acc[mt][nt][half * 2 + 1];
                    if (s0 < mv) { mv = s0; mj = col; }
                    if (s1 < mv) { mv = s1; mj = col + 1; }
                }
                #pragma unroll
                for (int o = 1; o < 4; o <<= 1) {
                    float ov = __shfl_xor_sync(0xffffffffu, mv, o);
                    int   oj = __shfl_xor_sync(0xffffffffu, mj, o);
                    if (ov < mv || (ov == mv && oj < mj)) { mv = ov; mj = oj; }
                }
                if ((lane & 3) == 0) {
                    g_pval[(size_t)row * NBW + chunk] = mv;
                    g_pidx[(size_t)row * NBW + chunk] = mj;
                }
            }
    } else {
        #pragma unroll
        for (int mt = 0; mt < MT; mt++)
            #pragma unroll
            for (int half = 0; half < 2; half++) {
                int row = bm + warp_m0 + mt * 16 + lr4 + half * 8;
                #pragma unroll
                for (int nt = 0; nt < 4; nt++) {
                    int col = bn + warp_n0 + nt * 8 + lc2;
                    float2 bv = *(const float2*)&bias[col];
                    float v0 = acc[mt][nt][half * 2 + 0] + bv.x;
                    float v1 = acc[mt][nt][half * 2 + 1] + bv.y;
                    size_t o = (size_t)row * N + col;
                    if (WHICH == 0) {
                        v0 = fmaxf(v0, 0.f); v1 = fmaxf(v1, 0.f);
                        __nv_bfloat16 h0, l0, h1, l1;
                        split_bf16(v0, h0, l0); split_bf16(v1, h1, l1);
                        *(__nv_bfloat162*)&g_hidH[o] = {h0, h1};
                        *(__nv_bfloat162*)&g_hidL[o] = {l0, l1};
                    } else {
                        *(float2*)&g_u[o] = make_float2(v0, v1);
                        out_ue[o] = v0; out_ue[o + 1] = v1;
                        __nv_bfloat16 h0, l0, h1, l1;
                        split_bf16(v0, h0, l0); split_bf16(v1, h1, l1);
                        *(__nv_bfloat162*)&g_uH[o] = {h0, h1};
                        *(__nv_bfloat162*)&g_uL[o] = {l0, l1};
                    }
                }
            }
    }
}

// ---------------------------------------------------------------------------
// Fused epilogue: per-row final argmin over 64 partials, then q=codebook[id];
// quant=u+(q-u); pos/neg gathers; diff partials.
// ---------------------------------------------------------------------------
__global__ void __launch_bounds__(128) epilogue_kernel(
    const float* __restrict__ codebook, const float* __restrict__ item_embed,
    const int* __restrict__ pos, const int* __restrict__ neg,
    float* __restrict__ out_q, float* __restrict__ out_pos,
    float* __restrict__ out_neg)
{
    int b = blockIdx.x;
    int t = threadIdx.x;

    __shared__ float pv[64];
    __shared__ int   pi[64];
    __shared__ int   s_id;
    if (t < 64) {
        pv[t] = g_pval[(size_t)b * NBW + t];
        pi[t] = g_pidx[(size_t)b * NBW + t];
    }
    __syncthreads();
    if (t < 32) {
        float v1 = pv[t]; int i1 = pi[t];
        float v2 = pv[t + 32]; int i2 = pi[t + 32];
        if (v2 < v1 || (v2 == v1 && i2 < i1)) { v1 = v2; i1 = i2; }
        #pragma unroll
        for (int o = 16; o > 0; o >>= 1) {
            float ov = __shfl_down_sync(0xffffffffu, v1, o);
            int   oi = __shfl_down_sync(0xffffffffu, i1, o);
            if (ov < v1 || (ov == v1 && oi < i1)) { v1 = ov; i1 = oi; }
        }
        if (t == 0) s_id = i1;
    }
    __syncthreads();
    int id = s_id;

    float4 q = ((const float4*)codebook)[(size_t)id * 128 + t];
    float4 u = ((const float4*)g_u)[(size_t)b * 128 + t];
    float4 d = make_float4(q.x - u.x, q.y - u.y, q.z - u.z, q.w - u.w);
    float4 qu = make_float4(u.x + d.x, u.y + d.y, u.z + d.z, u.w + d.w);
    ((float4*)out_q)[(size_t)b * 128 + t] = qu;

    int p = pos[b], n = neg[b];
    ((float4*)out_pos)[(size_t)b * 128 + t] = ((const float4*)item_embed)[(size_t)p * 128 + t];
    ((float4*)out_neg)[(size_t)b * 128 + t] = ((const float4*)item_embed)[(size_t)n * 128 + t];

    float ds = d.x * d.x + d.y * d.y + d.z * d.z + d.w * d.w;
    #pragma unroll
    for (int o = 16; o > 0; o >>= 1) ds += __shfl_down_sync(0xffffffffu, ds, o);
    __shared__ float red[4];
    if ((t & 31) == 0) red[t >> 5] = ds;
    __syncthreads();
    if (t == 0) g_bsum[b] = red[0] + red[1] + red[2] + red[3];
}

__global__ void __launch_bounds__(256) diff_kernel(float* __restrict__ out_diff)
{
    int t = threadIdx.x;
    float s = 0.f;
    #pragma unroll
    for (int i = 0; i < BB / 256; i++) s += g_bsum[t + i * 256];
    __shared__ float sv[256];
    sv[t] = s;
    __syncthreads();
    for (int o = 128; o > 0; o >>= 1) {
        if (t < o) sv[t] += sv[t + o];
        __syncthreads();
    }
    if (t == 0) *out_diff = sv[0] * (1.0f / (float)BD);
}

// ---------------------------------------------------------------------------
extern "C" void kernel_launch(void* const* d_in, const int* in_sizes, int n_in,
                              void* d_out, int out_size)
{
    const int*   items      = (const int*)  d_in[1];
    const int*   pos        = (const int*)  d_in[2];
    const int*   neg        = (const int*)  d_in[3];
    const float* item_embed = (const float*)d_in[4];
    const float* W1         = (const float*)d_in[5];
    const float* b1         = (const float*)d_in[6];
    const float* W2         = (const float*)d_in[7];
    const float* b2         = (const float*)d_in[8];
    const float* codebook   = (const float*)d_in[9];

    float* out      = (float*)d_out;
    float* out_q    = out;
    float* out_pos  = out + (size_t)BD;
    float* out_neg  = out + (size_t)2 * BD;
    float* out_diff = out + (size_t)3 * BD;
    float* out_ue   = out + (size_t)3 * BD + 1;

    const int SMEM_BIG   = 3 * 2 * (128 + 128) * 128;  // 196608 (3 stages)
    const int SMEM_SMALL = 3 * 2 * (128 + 64) * 128;   // 147456
    cudaFuncSetAttribute(gemm_mma<0>, cudaFuncAttributeMaxDynamicSharedMemorySize, SMEM_BIG);
    cudaFuncSetAttribute(gemm_mma<1>, cudaFuncAttributeMaxDynamicSharedMemorySize, SMEM_SMALL);
    cudaFuncSetAttribute(gemm_mma<2>, cudaFuncAttributeMaxDynamicSharedMemorySize, SMEM_BIG);

    __nv_bfloat16 *meanH, *meanL, *hidH, *hidL, *uH, *uL, *w1tH, *w1tL, *w2tH, *w2tL, *cbH, *cbL;
    cudaGetSymbolAddress((void**)&meanH, g_meanH);
    cudaGetSymbolAddress((void**)&meanL, g_meanL);
    cudaGetSymbolAddress((void**)&hidH,  g_hidH);
    cudaGetSymbolAddress((void**)&hidL,  g_hidL);
    cudaGetSymbolAddress((void**)&uH,    g_uH);
    cudaGetSymbolAddress((void**)&uL,    g_uL);
    cudaGetSymbolAddress((void**)&w1tH,  g_W1tH);
    cudaGetSymbolAddress((void**)&w1tL,  g_W1tL);
    cudaGetSymbolAddress((void**)&w2tH,  g_W2tH);
    cudaGetSymbolAddress((void**)&w2tL,  g_W2tL);
    cudaGetSymbolAddress((void**)&cbH,   g_cbH);
    cudaGetSymbolAddress((void**)&cbL,   g_cbL);

    // fused prep: gather(2048) | cnorm+cbsplit(2048) | W1t(512) | W2t(512)
    prep_kernel<<<5120, 128>>>(items, item_embed, codebook, W1, W2);

    gemm_mma<0><<<dim3(HHID / 128, BB / 128), 256, SMEM_BIG>>>(
        meanH, meanL, w1tH, w1tL, b1, nullptr, HHID, DD);
    gemm_mma<1><<<dim3(DD / 64,    BB / 128), 256, SMEM_SMALL>>>(
        hidH,  hidL,  w2tH, w2tL, b2, out_ue,  DD,  HHID);
    gemm_mma<2><<<dim3(CBK / 128,  BB / 128), 256, SMEM_BIG>>>(
        uH,    uL,    cbH,  cbL,  nullptr, nullptr, CBK, DD);

    epilogue_kernel<<<BB, 128>>>(codebook, item_embed, pos, neg, out_q, out_pos, out_neg);
    diff_kernel<<<1, 256>>>(out_diff);
}

// round 7
// speedup vs baseline: 2.2612x; 1.0002x over previous
#include <cuda_runtime.h>
#include <cuda_bf16.h>
#include <cstdint>

// Problem constants
#define BB    2048     // batch
#define KHIST 200      // history length
#define DD    512      // latent dim
#define HHID  1024     // 2*D
#define CBK   2048     // codebook size
#define BD    (BB*DD)  // 1048576
#define NBW   64       // CBK / 32 argmin partial chunks per row

// ---------------- scratch (device globals; no allocation allowed) ----------
__device__ float        g_u[BB * DD];
__device__ float        g_cnorm[CBK];
__device__ float        g_pval[BB * NBW];
__device__ int          g_pidx[BB * NBW];
__device__ float        g_bsum[BB];
__device__ int          g_count;          // zero-init; self-resetting

// bf16 hi/lo split operands
__device__ __nv_bfloat16 g_meanH[BB * DD],   g_meanL[BB * DD];     // [2048,512]
__device__ __nv_bfloat16 g_hidH [BB * HHID], g_hidL [BB * HHID];   // [2048,1024]
__device__ __nv_bfloat16 g_uH   [BB * DD],   g_uL   [BB * DD];     // [2048,512]
__device__ __nv_bfloat16 g_W1tH [HHID * DD], g_W1tL [HHID * DD];   // [1024,512] (=W1^T)
__device__ __nv_bfloat16 g_W2tH [DD * HHID], g_W2tL [DD * HHID];   // [512,1024] (=W2^T)
__device__ __nv_bfloat16 g_cbH  [CBK * DD],  g_cbL  [CBK * DD];    // [2048,512]

// ---------------------------------------------------------------------------
// Portable PTX helpers (sm_80+; ptxas here targets plain sm_103 — no tcgen05)
// ---------------------------------------------------------------------------
__device__ __forceinline__ uint32_t smem_u32(const void* p) {
    uint32_t a;
    asm("{ .reg .u64 t; cvta.to.shared.u64 t, %1; cvt.u32.u64 %0, t; }" : "=r"(a) : "l"(p));
    return a;
}

#define CP_ASYNC16(dst, src) \
    asm volatile("cp.async.cg.shared.global [%0], [%1], 16;" :: "r"(dst), "l"(src))
#define CP_COMMIT() asm volatile("cp.async.commit_group;" ::: "memory")
#define CP_WAIT0()  asm volatile("cp.async.wait_group 0;" ::: "memory")
#define CP_WAIT1()  asm volatile("cp.async.wait_group 1;" ::: "memory")

__device__ __forceinline__ void ldsm4(uint32_t (&r)[4], uint32_t addr) {
    asm volatile("ldmatrix.sync.aligned.m8n8.x4.shared.b16 {%0,%1,%2,%3}, [%4];"
                 : "=r"(r[0]), "=r"(r[1]), "=r"(r[2]), "=r"(r[3]) : "r"(addr));
}

__device__ __forceinline__ void mma16816(float (&d)[4], const uint32_t (&a)[4],
                                         uint32_t b0, uint32_t b1) {
    asm volatile(
        "mma.sync.aligned.m16n8k16.row.col.f32.bf16.bf16.f32 "
        "{%0,%1,%2,%3}, {%4,%5,%6,%7}, {%8,%9}, {%0,%1,%2,%3};"
        : "+f"(d[0]), "+f"(d[1]), "+f"(d[2]), "+f"(d[3])
        : "r"(a[0]), "r"(a[1]), "r"(a[2]), "r"(a[3]), "r"(b0), "r"(b1));
}

__device__ __forceinline__ void split_bf16(float v, __nv_bfloat16& h, __nv_bfloat16& l) {
    h = __float2bfloat16(v);
    l = __float2bfloat16(v - __bfloat162float(h));
}

// ---------------------------------------------------------------------------
// Fused PREP megakernel:
//   blocks [0,2048)      : masked gather + mean -> g_meanH/L
//   blocks [2048,4096)   : codebook norms + hi/lo split
//   blocks [4096,4608)   : W1^T hi/lo split
//   blocks [4608,5120)   : W2^T hi/lo split
// ---------------------------------------------------------------------------
__global__ void __launch_bounds__(128) prep_kernel(
    const int* __restrict__ items, const float* __restrict__ item_embed,
    const float* __restrict__ codebook,
    const float* __restrict__ W1, const float* __restrict__ W2)
{
    __shared__ int   sidx[KHIST];
    __shared__ float ts[32][33];
    __shared__ float red[4];

    const int blk = blockIdx.x;
    const int t = threadIdx.x;

    if (blk < 2048) {
        int b = blk;
        for (int i = t; i < KHIST; i += 128) sidx[i] = items[b * KHIST + i];
        __syncthreads();
        const float4* E4 = (const float4*)item_embed;
        float4 acc = make_float4(0.f, 0.f, 0.f, 0.f);
        int cnt = 0;
        #pragma unroll 4
        for (int k = 0; k < KHIST; k++) {
            int idx = sidx[k];
            float m = (idx != 0) ? 1.0f : 0.0f;
            cnt += (idx != 0);
            float4 v = E4[(size_t)idx * 128 + t];
            acc.x += m * v.x; acc.y += m * v.y; acc.z += m * v.z; acc.w += m * v.w;
        }
        float inv = 1.0f / (float)cnt;
        float vals[4] = {acc.x * inv, acc.y * inv, acc.z * inv, acc.w * inv};
        size_t base = (size_t)b * DD + t * 4;
        __nv_bfloat16 h[4], l[4];
        #pragma unroll
        for (int i = 0; i < 4; i++) split_bf16(vals[i], h[i], l[i]);
        *(__nv_bfloat162*)&g_meanH[base]     = {h[0], h[1]};
        *(__nv_bfloat162*)&g_meanH[base + 2] = {h[2], h[3]};
        *(__nv_bfloat162*)&g_meanL[base]     = {l[0], l[1]};
        *(__nv_bfloat162*)&g_meanL[base + 2] = {l[2], l[3]};
    } else if (blk < 4096) {
        int j = blk - 2048;
        float4 v = ((const float4*)codebook)[j * 128 + t];
        float vals[4] = {v.x, v.y, v.z, v.w};
        size_t base = (size_t)j * DD + t * 4;
        __nv_bfloat16 h[4], l[4];
        #pragma unroll
        for (int i = 0; i < 4; i++) split_bf16(vals[i], h[i], l[i]);
        *(__nv_bfloat162*)&g_cbH[base]     = {h[0], h[1]};
        *(__nv_bfloat162*)&g_cbH[base + 2] = {h[2], h[3]};
        *(__nv_bfloat162*)&g_cbL[base]     = {l[0], l[1]};
        *(__nv_bfloat162*)&g_cbL[base + 2] = {l[2], l[3]};

        float s = v.x * v.x + v.y * v.y + v.z * v.z + v.w * v.w;
        #pragma unroll
        for (int o = 16; o > 0; o >>= 1) s += __shfl_down_sync(0xffffffffu, s, o);
        if ((t & 31) == 0) red[t >> 5] = s;
        __syncthreads();
        if (t == 0) g_cnorm[j] = red[0] + red[1] + red[2] + red[3];
    } else {
        const float* W;
        __nv_bfloat16 *WtH, *WtL;
        int KD, ND, w;
        if (blk < 4608) {
            w = blk - 4096; W = W1; WtH = g_W1tH; WtL = g_W1tL; KD = DD; ND = HHID;
        } else {
            w = blk - 4608; W = W2; WtH = g_W2tH; WtL = g_W2tL; KD = HHID; ND = DD;
        }
        int nblk = ND / 32;
        int n0 = (w % nblk) * 32, k0 = (w / nblk) * 32;
        int tx = t & 31, ty = t >> 5;
        #pragma unroll
        for (int i = ty; i < 32; i += 4)
            ts[i][tx] = W[(size_t)(k0 + i) * ND + n0 + tx];
        __syncthreads();
        #pragma unroll
        for (int i = ty; i < 32; i += 4) {
            float v = ts[tx][i];
            __nv_bfloat16 h, l;
            split_bf16(v, h, l);
            size_t o = (size_t)(n0 + i) * KD + k0 + tx;
            WtH[o] = h;
            WtL[o] = l;
        }
    }
}

// ---------------------------------------------------------------------------
// Tensor-core GEMM (mma.sync bf16x3, fp32 accum): C = A[M,Kd] @ B[N,Kd]^T
// BM x 64 CTA tile, 8 warps (4x2), warp tile (BM/4) x 32, K-chunks of 64
// halves, SW128-swizzled smem, 2-stage cp.async, multi-CTA/SM residency.
// WHICH=0: hid = relu(mean @ W1t^T + b1)  BM=128 -> g_hidH/L
// WHICH=1: u   = hid @ W2t^T + b2         BM=64  -> g_u, out_ue, g_uH/L
// WHICH=2: fused scores+argmin partials   BM=128 -> g_pval/g_pidx
// ---------------------------------------------------------------------------
template<int BM, int WHICH>
__global__ void __launch_bounds__(256, (BM == 64) ? 3 : 2) gemm_mma(
    const __nv_bfloat16* __restrict__ Ah, const __nv_bfloat16* __restrict__ Al,
    const __nv_bfloat16* __restrict__ Bh, const __nv_bfloat16* __restrict__ Bl,
    const float* __restrict__ bias, float* __restrict__ out_ue,
    int N, int Kd)
{
    constexpr int BN  = 64;
    constexpr int WM  = BM / 4;           // 32 or 16
    constexpr int MT  = WM / 16;          // 2 or 1
    constexpr int STAGE = 2 * (BM + BN) * 128;   // bytes per pipeline stage

    extern __shared__ char smem[];
    const uint32_t sbase = smem_u32(smem);
    const int tid  = threadIdx.x;
    const int lane = tid & 31;
    const int w    = tid >> 5;
    const int warp_m0 = (w >> 1) * WM;
    const int warp_n0 = (w & 1) * 32;
    const int bm = blockIdx.y * BM, bn = blockIdx.x * BN;

    // ---- gmem -> smem stage loader (cp.async, SW128 swizzle) ----
    auto loadT = [&](const __nv_bfloat16* __restrict__ src, int row0, int k0,
                     uint32_t dst, int R) {
        #pragma unroll 4
        for (int i = 0; i < R * 8; i += 256) {
            int u = tid + i;
            int r = u >> 3, c8 = u & 7;
            uint32_t sd = dst + r * 128 + ((c8 * 16) ^ ((r & 7) << 4));
            const __nv_bfloat16* gs = src + (size_t)(row0 + r) * Kd + k0 + c8 * 8;
            CP_ASYNC16(sd, gs);
        }
    };
    auto issue = [&](int c, int buf) {
        uint32_t sb = sbase + (uint32_t)buf * STAGE;
        int k0 = c * 64;
        loadT(Ah, bm, k0, sb, BM);
        loadT(Al, bm, k0, sb + BM * 128, BM);
        loadT(Bh, bn, k0, sb + 2 * BM * 128, BN);
        loadT(Bl, bn, k0, sb + 2 * BM * 128 + BN * 128, BN);
    };

    // ---- per-lane ldmatrix address components ----
    const int tile = lane >> 3, lr = lane & 7;
    const uint32_t xorp = (uint32_t)(lr << 4);
    const int aRow = warp_m0 + ((tile & 1) << 3) + lr;
    const uint32_t aK = (uint32_t)((tile >> 1) << 4);
    const int bRow = warp_n0 + ((tile >> 1) << 3) + lr;
    const uint32_t bK = (uint32_t)((tile & 1) << 4);

    float acc[MT][4][4] = {};

    const int NC = Kd / 64;
    issue(0, 0); CP_COMMIT();
    issue(1, 1); CP_COMMIT();
    CP_WAIT1();
    __syncthreads();

    for (int c = 0; c < NC; c++) {
        uint32_t s0 = sbase + (uint32_t)(c & 1) * STAGE;
        uint32_t pA[2] = { s0, s0 + BM * 128 };
        uint32_t pB[2] = { s0 + 2 * BM * 128, s0 + 2 * BM * 128 + BN * 128 };

        #pragma unroll
        for (int kk = 0; kk < 4; kk++) {
            uint32_t akb = (((uint32_t)kk << 5) + aK) ^ xorp;
            uint32_t bkb = (((uint32_t)kk << 5) + bK) ^ xorp;
            uint32_t a[2][MT][4];
            uint32_t b[2][4][2];
            #pragma unroll
            for (int s = 0; s < 2; s++)
                #pragma unroll
                for (int mt = 0; mt < MT; mt++)
                    ldsm4(a[s][mt], pA[s] + (uint32_t)(aRow + mt * 16) * 128 + akb);
            #pragma unroll
            for (int s = 0; s < 2; s++)
                #pragma unroll
                for (int ng = 0; ng < 2; ng++) {
                    uint32_t t4[4];
                    ldsm4(t4, pB[s] + (uint32_t)(bRow + ng * 16) * 128 + bkb);
                    b[s][2 * ng][0] = t4[0]; b[s][2 * ng][1] = t4[1];
                    b[s][2 * ng + 1][0] = t4[2]; b[s][2 * ng + 1][1] = t4[3];
                }
            #pragma unroll
            for (int mt = 0; mt < MT; mt++)
                #pragma unroll
                for (int nt = 0; nt < 4; nt++)
                    mma16816(acc[mt][nt], a[0][mt], b[0][nt][0], b[0][nt][1]);
            #pragma unroll
            for (int mt = 0; mt < MT; mt++)
                #pragma unroll
                for (int nt = 0; nt < 4; nt++)
                    mma16816(acc[mt][nt], a[0][mt], b[1][nt][0], b[1][nt][1]);
            #pragma unroll
            for (int mt = 0; mt < MT; mt++)
                #pragma unroll
                for (int nt = 0; nt < 4; nt++)
                    mma16816(acc[mt][nt], a[1][mt], b[0][nt][0], b[0][nt][1]);
        }

        if (c == NC - 1) break;
        __syncthreads();
        if (c + 2 < NC) { issue(c + 2, c & 1); CP_COMMIT(); CP_WAIT1(); }
        else            { CP_WAIT0(); }
        __syncthreads();
    }

    // ---------------- epilogue (registers -> gmem) ----------------
    const int lr4 = lane >> 2;          // 0..7
    const int lc2 = (lane & 3) * 2;     // 0,2,4,6

    if (WHICH == 2) {
        int chunk = (bn + warp_n0) >> 5;
        #pragma unroll
        for (int mt = 0; mt < MT; mt++)
            #pragma unroll
            for (int half = 0; half < 2; half++) {
                int row = bm + warp_m0 + mt * 16 + lr4 + half * 8;
                float mv = 3.0e38f; int mj = 0x7fffffff;
                #pragma unroll
                for (int nt = 0; nt < 4; nt++) {
                    int col = bn + warp_n0 + nt * 8 + lc2;
                    float2 cn = *(const float2*)&g_cnorm[col];
                    float s0 = cn.x - 2.0f * acc[mt][nt][half * 2 + 0];
                    float s1 = cn.y - 2.0f * acc[mt][nt][half * 2 + 1];
                    if (s0 < mv) { mv = s0; mj = col; }
                    if (s1 < mv) { mv = s1; mj = col + 1; }
                }
                #pragma unroll
                for (int o = 1; o < 4; o <<= 1) {
                    float ov = __shfl_xor_sync(0xffffffffu, mv, o);
                    int   oj = __shfl_xor_sync(0xffffffffu, mj, o);
                    if (ov < mv || (ov == mv && oj < mj)) { mv = ov; mj = oj; }
                }
                if ((lane & 3) == 0) {
                    g_pval[(size_t)row * NBW + chunk] = mv;
                    g_pidx[(size_t)row * NBW + chunk] = mj;
                }
            }
    } else {
        #pragma unroll
        for (int mt = 0; mt < MT; mt++)
            #pragma unroll
            for (int half = 0; half < 2; half++) {
                int row = bm + warp_m0 + mt * 16 + lr4 + half * 8;
                #pragma unroll
                for (int nt = 0; nt < 4; nt++) {
                    int col = bn + warp_n0 + nt * 8 + lc2;
                    float2 bv = *(const float2*)&bias[col];
                    float v0 = acc[mt][nt][half * 2 + 0] + bv.x;
                    float v1 = acc[mt][nt][half * 2 + 1] + bv.y;
                    size_t o = (size_t)row * N + col;
                    if (WHICH == 0) {
                        v0 = fmaxf(v0, 0.f); v1 = fmaxf(v1, 0.f);
                        __nv_bfloat16 h0, l0, h1, l1;
                        split_bf16(v0, h0, l0); split_bf16(v1, h1, l1);
                        *(__nv_bfloat162*)&g_hidH[o] = {h0, h1};
                        *(__nv_bfloat162*)&g_hidL[o] = {l0, l1};
                    } else {
                        *(float2*)&g_u[o] = make_float2(v0, v1);
                        out_ue[o] = v0; out_ue[o + 1] = v1;
                        __nv_bfloat16 h0, l0, h1, l1;
                        split_bf16(v0, h0, l0); split_bf16(v1, h1, l1);
                        *(__nv_bfloat162*)&g_uH[o] = {h0, h1};
                        *(__nv_bfloat162*)&g_uL[o] = {l0, l1};
                    }
                }
            }
    }
}

// ---------------------------------------------------------------------------
// Fused epilogue: per-row final argmin over 64 partials, then q=codebook[id];
// quant=u+(q-u); pos/neg gathers; diff partials; deterministic last-block
// reduction of diff (counter self-resets for graph replay).
// ---------------------------------------------------------------------------
__global__ void __launch_bounds__(128) epilogue_kernel(
    const float* __restrict__ codebook, const float* __restrict__ item_embed,
    const int* __restrict__ pos, const int* __restrict__ neg,
    float* __restrict__ out_q, float* __restrict__ out_pos,
    float* __restrict__ out_neg, float* __restrict__ out_diff)
{
    int b = blockIdx.x;
    int t = threadIdx.x;

    __shared__ float pv[64];
    __shared__ int   pi[64];
    __shared__ int   s_id;
    __shared__ bool  s_last;
    if (t < 64) {
        pv[t] = g_pval[(size_t)b * NBW + t];
        pi[t] = g_pidx[(size_t)b * NBW + t];
    }
    __syncthreads();
    if (t < 32) {
        float v1 = pv[t]; int i1 = pi[t];
        float v2 = pv[t + 32]; int i2 = pi[t + 32];
        if (v2 < v1 || (v2 == v1 && i2 < i1)) { v1 = v2; i1 = i2; }
        #pragma unroll
        for (int o = 16; o > 0; o >>= 1) {
            float ov = __shfl_down_sync(0xffffffffu, v1, o);
            int   oi = __shfl_down_sync(0xffffffffu, i1, o);
            if (ov < v1 || (ov == v1 && oi < i1)) { v1 = ov; i1 = oi; }
        }
        if (t == 0) s_id = i1;
    }
    __syncthreads();
    int id = s_id;

    float4 q = ((const float4*)codebook)[(size_t)id * 128 + t];
    float4 u = ((const float4*)g_u)[(size_t)b * 128 + t];
    float4 d = make_float4(q.x - u.x, q.y - u.y, q.z - u.z, q.w - u.w);
    float4 qu = make_float4(u.x + d.x, u.y + d.y, u.z + d.z, u.w + d.w);
    ((float4*)out_q)[(size_t)b * 128 + t] = qu;

    int p = pos[b], n = neg[b];
    ((float4*)out_pos)[(size_t)b * 128 + t] = ((const float4*)item_embed)[(size_t)p * 128 + t];
    ((float4*)out_neg)[(size_t)b * 128 + t] = ((const float4*)item_embed)[(size_t)n * 128 + t];

    float ds = d.x * d.x + d.y * d.y + d.z * d.z + d.w * d.w;
    #pragma unroll
    for (int o = 16; o > 0; o >>= 1) ds += __shfl_down_sync(0xffffffffu, ds, o);
    __shared__ float red[4];
    if ((t & 31) == 0) red[t >> 5] = ds;
    __syncthreads();
    if (t == 0) {
        g_bsum[b] = red[0] + red[1] + red[2] + red[3];
        __threadfence();
        int c = atomicAdd(&g_count, 1);
        s_last = (c == BB - 1);
    }
    __syncthreads();

    if (s_last) {
        // deterministic fixed-tree reduction over all 2048 partials
        float s = 0.f;
        #pragma unroll
        for (int i = 0; i < BB / 128; i++) s += g_bsum[t + i * 128];
        __shared__ float sv[128];
        sv[t] = s;
        __syncthreads();
        for (int o = 64; o > 0; o >>= 1) {
            if (t < o) sv[t] += sv[t + o];
            __syncthreads();
        }
        if (t == 0) {
            *out_diff = sv[0] * (1.0f / (float)BD);
            g_count = 0;                       // reset for next graph replay
        }
    }
}

// ---------------------------------------------------------------------------
extern "C" void kernel_launch(void* const* d_in, const int* in_sizes, int n_in,
                              void* d_out, int out_size)
{
    const int*   items      = (const int*)  d_in[1];
    const int*   pos        = (const int*)  d_in[2];
    const int*   neg        = (const int*)  d_in[3];
    const float* item_embed = (const float*)d_in[4];
    const float* W1         = (const float*)d_in[5];
    const float* b1         = (const float*)d_in[6];
    const float* W2         = (const float*)d_in[7];
    const float* b2         = (const float*)d_in[8];
    const float* codebook   = (const float*)d_in[9];

    float* out      = (float*)d_out;
    float* out_q    = out;
    float* out_pos  = out + (size_t)BD;
    float* out_neg  = out + (size_t)2 * BD;
    float* out_diff = out + (size_t)3 * BD;
    float* out_ue   = out + (size_t)3 * BD + 1;

    const int SMEM_128 = 2 * 2 * (128 + 64) * 128;  // 98304 (2 stages)
    const int SMEM_64  = 2 * 2 * (64 + 64) * 128;   // 65536
    cudaFuncSetAttribute((const void*)gemm_mma<128, 0>,
                         cudaFuncAttributeMaxDynamicSharedMemorySize, SMEM_128);
    cudaFuncSetAttribute((const void*)gemm_mma<64, 1>,
                         cudaFuncAttributeMaxDynamicSharedMemorySize, SMEM_64);
    cudaFuncSetAttribute((const void*)gemm_mma<128, 2>,
                         cudaFuncAttributeMaxDynamicSharedMemorySize, SMEM_128);

    __nv_bfloat16 *meanH, *meanL, *hidH, *hidL, *uH, *uL, *w1tH, *w1tL, *w2tH, *w2tL, *cbH, *cbL;
    cudaGetSymbolAddress((void**)&meanH, g_meanH);
    cudaGetSymbolAddress((void**)&meanL, g_meanL);
    cudaGetSymbolAddress((void**)&hidH,  g_hidH);
    cudaGetSymbolAddress((void**)&hidL,  g_hidL);
    cudaGetSymbolAddress((void**)&uH,    g_uH);
    cudaGetSymbolAddress((void**)&uL,    g_uL);
    cudaGetSymbolAddress((void**)&w1tH,  g_W1tH);
    cudaGetSymbolAddress((void**)&w1tL,  g_W1tL);
    cudaGetSymbolAddress((void**)&w2tH,  g_W2tH);
    cudaGetSymbolAddress((void**)&w2tL,  g_W2tL);
    cudaGetSymbolAddress((void**)&cbH,   g_cbH);
    cudaGetSymbolAddress((void**)&cbL,   g_cbL);

    // fused prep: gather(2048) | cnorm+cbsplit(2048) | W1t(512) | W2t(512)
    prep_kernel<<<5120, 128>>>(items, item_embed, codebook, W1, W2);

    gemm_mma<128, 0><<<dim3(HHID / 64, BB / 128), 256, SMEM_128>>>(
        meanH, meanL, w1tH, w1tL, b1, nullptr, HHID, DD);
    gemm_mma<64, 1><<<dim3(DD / 64, BB / 64), 256, SMEM_64>>>(
        hidH,  hidL,  w2tH, w2tL, b2, out_ue,  DD,  HHID);
    gemm_mma<128, 2><<<dim3(CBK / 64, BB / 128), 256, SMEM_128>>>(
        uH,    uL,    cbH,  cbL,  nullptr, nullptr, CBK, DD);

    epilogue_kernel<<<BB, 128>>>(codebook, item_embed, pos, neg,
                                 out_q, out_pos, out_neg, out_diff);
}